// round 13
// baseline (speedup 1.0000x reference)
#include <cuda_runtime.h>
#include <cuda_bf16.h>
#include <math.h>
#include <stdint.h>

// Problem constants
#define N_NODES 50000
#define N_EDGES 800000
#define IN_CH   128
#define HID     256
#define OUT_CH  40

// -------- static device scratch (allocation-free) --------
__device__ float g_buf0[(size_t)N_NODES * HID];
__device__ float g_buf1[(size_t)N_NODES * HID];
__device__ float g_buf2[(size_t)N_NODES * HID];

// tf32-rounded weights
__device__ float g_w1[IN_CH * HID];
__device__ float g_w2[HID * HID];
__device__ float g_w3[HID * OUT_CH];

// CSR-by-dst scratch (packed: .x = src, .y = float-bits of weight)
#define NSB ((N_NODES + 255) / 256)   // 196 scan blocks
__device__ int   g_deg[N_NODES];
__device__ int   g_off[N_NODES + 1];
__device__ int   g_pos[N_NODES];
__device__ int   g_bsum[NSB];
__device__ int   g_boff[NSB];
__device__ int2  g_csr[N_EDGES];

__device__ __forceinline__ float rnd_tf32(float f) {
    uint32_t r;
    asm("cvt.rna.tf32.f32 %0, %1;" : "=r"(r) : "f"(f));
    return __uint_as_float(r);
}

// =========================================================
// tf32 tensor-core GEMM: C[M,N] = A[M,K] @ B[K,N]
// A and B must be tf32-pre-rounded fp32.
// EPI: 0 = plain store, 1 = rnd_tf32(relu(acc + bias[n]))
// BN: block N-tile (128 or 64). Block 128xBNx32, 8 warps (4M x 2N),
// warp tile 32 x BN/2. A k-major + XOR swizzle (R4 proven layout),
// register-prefetch double buffering, no cvt in hot path.
// =========================================================
#define GBM 128
#define GBK 32
#define ASTRIDE 136

__device__ __forceinline__ void mma_tf32(float* d, const uint32_t* a, const uint32_t* b) {
    asm volatile(
        "mma.sync.aligned.m16n8k8.row.col.f32.tf32.tf32.f32 "
        "{%0,%1,%2,%3}, {%4,%5,%6,%7}, {%8,%9}, {%0,%1,%2,%3};\n"
        : "+f"(d[0]), "+f"(d[1]), "+f"(d[2]), "+f"(d[3])
        : "r"(a[0]), "r"(a[1]), "r"(a[2]), "r"(a[3]),
          "r"(b[0]), "r"(b[1]));
}

template <int EPI, int BN>
__global__ __launch_bounds__(256) void gemm_tf32(
    const float* __restrict__ A, const float* __restrict__ B,
    const float* __restrict__ bias, float* __restrict__ C,
    int M, int N, int K)
{
    constexpr int BSTR   = BN + 8;     // word stride, %32 == 8 (conflict-free phases)
    constexpr int NJ     = BN / 16;    // 8-col groups per warp (warp N-tile = BN/2)
    constexpr int NB4    = BN / 32;    // B float4 loads per thread
    constexpr int BLANES = BN / 4;     // float4 lanes per B row

    __shared__ __align__(16) float As[GBK * ASTRIDE];
    __shared__ __align__(16) float Bs[GBK * BSTR];

    const int tid  = threadIdx.x;
    const int warp = tid >> 5;
    const int lane = tid & 31;
    const int bm = blockIdx.y * GBM;
    const int bn = blockIdx.x * BN;

    const int wm = (warp >> 1) * 32;
    const int wn = (warp & 1) * (BN / 2);
    const int qr = lane >> 2;
    const int qc = lane & 3;

    const int ar  = tid >> 3;          // A base row (i*32 added)
    const int ac4 = (tid & 7) * 4;     // A k-offset

    float acc[2][NJ][4];
#pragma unroll
    for (int i = 0; i < 2; i++)
#pragma unroll
        for (int j = 0; j < NJ; j++)
#pragma unroll
            for (int t = 0; t < 4; t++) acc[i][j][t] = 0.f;

    float4 ra[4], rb[NB4];

    // ---- preload tile k0 = 0 ----
#pragma unroll
    for (int i = 0; i < 4; i++) {
        int gr = bm + ar + i * 32;
        ra[i] = (gr < M)
            ? *reinterpret_cast<const float4*>(A + (long)gr * K + ac4)
            : make_float4(0.f, 0.f, 0.f, 0.f);
    }
#pragma unroll
    for (int i = 0; i < NB4; i++) {
        int idx  = tid + i * 256;
        int krow = idx / BLANES;
        int bc4  = (idx % BLANES) * 4;
        int gc = bn + bc4;
        float4 v = make_float4(0.f, 0.f, 0.f, 0.f);
        if (gc + 3 < N) {
            v = *reinterpret_cast<const float4*>(B + (long)krow * N + gc);
        } else {
            float* pv = &v.x;
#pragma unroll
            for (int j = 0; j < 4; j++)
                if (gc + j < N) pv[j] = B[(long)krow * N + gc + j];
        }
        rb[i] = v;
    }

    for (int k0 = 0; k0 < K; k0 += GBK) {
        // ---- store regs -> smem ----
#pragma unroll
        for (int i = 0; i < 4; i++) {
            int row = ar + i * 32;
            int sm = row ^ (((ac4 >> 2) & 7) << 3);
            const float* pv = &ra[i].x;
#pragma unroll
            for (int j = 0; j < 4; j++)
                As[(ac4 + j) * ASTRIDE + sm] = pv[j];
        }
#pragma unroll
        for (int i = 0; i < NB4; i++) {
            int idx  = tid + i * 256;
            int krow = idx / BLANES;
            int bc4  = (idx % BLANES) * 4;
            *reinterpret_cast<float4*>(&Bs[krow * BSTR + bc4]) = rb[i];
        }
        __syncthreads();

        // ---- prefetch next tile while mma runs ----
        if (k0 + GBK < K) {
            int kn = k0 + GBK;
#pragma unroll
            for (int i = 0; i < 4; i++) {
                int gr = bm + ar + i * 32;
                ra[i] = (gr < M)
                    ? *reinterpret_cast<const float4*>(A + (long)gr * K + kn + ac4)
                    : make_float4(0.f, 0.f, 0.f, 0.f);
            }
#pragma unroll
            for (int i = 0; i < NB4; i++) {
                int idx  = tid + i * 256;
                int krow = idx / BLANES;
                int bc4  = (idx % BLANES) * 4;
                int gc = bn + bc4;
                float4 v = make_float4(0.f, 0.f, 0.f, 0.f);
                if (gc + 3 < N) {
                    v = *reinterpret_cast<const float4*>(B + (long)(kn + krow) * N + gc);
                } else {
                    float* pv = &v.x;
#pragma unroll
                    for (int j = 0; j < 4; j++)
                        if (gc + j < N) pv[j] = B[(long)(kn + krow) * N + gc + j];
                }
                rb[i] = v;
            }
        }

        // ---- 4 k8-steps ----
#pragma unroll
        for (int ks = 0; ks < 4; ks++) {
            int kb = ks * 8;
            int kA0 = kb + qc;
            int kA1 = kb + qc + 4;
            int sw0 = ((kA0 >> 2) & 7) << 3;
            int sw1 = ((kA1 >> 2) & 7) << 3;

            uint32_t a[2][4];
#pragma unroll
            for (int i = 0; i < 2; i++) {
                int mb = wm + i * 16;
                a[i][0] = __float_as_uint(As[kA0 * ASTRIDE + ((mb + qr)     ^ sw0)]);
                a[i][1] = __float_as_uint(As[kA0 * ASTRIDE + ((mb + qr + 8) ^ sw0)]);
                a[i][2] = __float_as_uint(As[kA1 * ASTRIDE + ((mb + qr)     ^ sw1)]);
                a[i][3] = __float_as_uint(As[kA1 * ASTRIDE + ((mb + qr + 8) ^ sw1)]);
            }
            uint32_t b[NJ][2];
#pragma unroll
            for (int j = 0; j < NJ; j++) {
                int nb = wn + j * 8;
                b[j][0] = __float_as_uint(Bs[(kb + qc)     * BSTR + nb + qr]);
                b[j][1] = __float_as_uint(Bs[(kb + qc + 4) * BSTR + nb + qr]);
            }
#pragma unroll
            for (int i = 0; i < 2; i++)
#pragma unroll
                for (int j = 0; j < NJ; j++)
                    mma_tf32(acc[i][j], a[i], b[j]);
        }
        __syncthreads();
    }

    // ---- epilogue ----
#pragma unroll
    for (int i = 0; i < 2; i++) {
        int r0 = bm + wm + i * 16 + qr;
        int r1 = r0 + 8;
#pragma unroll
        for (int j = 0; j < NJ; j++) {
            int c0 = bn + wn + j * 8 + qc * 2;
            float v0 = acc[i][j][0], v1 = acc[i][j][1];
            float v2 = acc[i][j][2], v3 = acc[i][j][3];
            if (EPI == 1) {
                float bb0 = (c0 < N) ? bias[c0] : 0.f;
                float bb1 = (c0 + 1 < N) ? bias[c0 + 1] : 0.f;
                v0 = rnd_tf32(fmaxf(v0 + bb0, 0.f));
                v1 = rnd_tf32(fmaxf(v1 + bb1, 0.f));
                v2 = rnd_tf32(fmaxf(v2 + bb0, 0.f));
                v3 = rnd_tf32(fmaxf(v3 + bb1, 0.f));
            }
            if (r0 < M) {
                if (c0     < N) C[(long)r0 * N + c0]     = v0;
                if (c0 + 1 < N) C[(long)r0 * N + c0 + 1] = v1;
            }
            if (r1 < M) {
                if (c0     < N) C[(long)r1 * N + c0]     = v2;
                if (c0 + 1 < N) C[(long)r1 * N + c0 + 1] = v3;
            }
        }
    }
}

// =========================================================
// weight prep: round to tf32
// =========================================================
__global__ void prep_kernel(const float* __restrict__ W1,
                            const float* __restrict__ W2,
                            const float* __restrict__ W3)
{
    int i = blockIdx.x * blockDim.x + threadIdx.x;
    if (i < IN_CH * HID)  g_w1[i] = rnd_tf32(W1[i]);
    if (i < HID * HID)    g_w2[i] = rnd_tf32(W2[i]);
    if (i < HID * OUT_CH) g_w3[i] = rnd_tf32(W3[i]);
}

// =========================================================
// CSR build: hist -> 3-stage parallel scan -> fill
// =========================================================
__global__ void zero_deg_kernel()
{
    int i = blockIdx.x * blockDim.x + threadIdx.x;
    if (i < N_NODES) g_deg[i] = 0;
}

__global__ void hist_kernel(const int* __restrict__ dst)
{
    int e = blockIdx.x * blockDim.x + threadIdx.x;
    if (e < N_EDGES) atomicAdd(&g_deg[dst[e]], 1);
}

__global__ __launch_bounds__(256) void scan_block_kernel()
{
    __shared__ int s[256];
    int t = threadIdx.x;
    int i = blockIdx.x * 256 + t;
    int v = (i < N_NODES) ? g_deg[i] : 0;
    s[t] = v;
    __syncthreads();
#pragma unroll
    for (int o = 1; o < 256; o <<= 1) {
        int add = (t >= o) ? s[t - o] : 0;
        __syncthreads();
        s[t] += add;
        __syncthreads();
    }
    if (i < N_NODES) g_off[i] = s[t] - v;
    if (t == 255) g_bsum[blockIdx.x] = s[255];
}

__global__ __launch_bounds__(256) void scan_top_kernel()
{
    __shared__ int s[256];
    int t = threadIdx.x;
    int v = (t < NSB) ? g_bsum[t] : 0;
    s[t] = v;
    __syncthreads();
#pragma unroll
    for (int o = 1; o < 256; o <<= 1) {
        int add = (t >= o) ? s[t - o] : 0;
        __syncthreads();
        s[t] += add;
        __syncthreads();
    }
    if (t < NSB) g_boff[t] = s[t] - v;
}

__global__ void scan_finalize_kernel()
{
    int i = blockIdx.x * blockDim.x + threadIdx.x;
    if (i < N_NODES) {
        int o = g_off[i] + g_boff[i >> 8];
        g_off[i] = o;
        g_pos[i] = o;
    }
    if (i == 0) g_off[N_NODES] = N_EDGES;
}

__global__ void fill_kernel(const int* __restrict__ src,
                            const int* __restrict__ dst,
                            const float* __restrict__ ew)
{
    int e = blockIdx.x * blockDim.x + threadIdx.x;
    if (e >= N_EDGES) return;
    int p = atomicAdd(&g_pos[dst[e]], 1);
    g_csr[p] = make_int2(src[e], __float_as_int(ew[e]));
}

// =========================================================
// CSR gather: agg[n] = sum_{e} w_e * h[src_e]
// EPI: 0 = rnd_tf32(acc), 1 = rnd_tf32(relu(acc + bias[ch]))
// =========================================================
template <int C4, int EPI>
__global__ __launch_bounds__(256) void gather_kernel(
    const float* __restrict__ h, const float* __restrict__ bias,
    float* __restrict__ agg)
{
    const int SLICES = C4 / 32;
    int gw = (int)(((long)blockIdx.x * blockDim.x + threadIdx.x) >> 5);
    int lane = threadIdx.x & 31;
    int n = gw / SLICES;
    int sl = gw - n * SLICES;
    if (n >= N_NODES) return;
    int c = sl * 32 + lane;

    const float4* hp = reinterpret_cast<const float4*>(h);
    int e   = g_off[n];
    int end = g_off[n + 1];

    float4 acc = make_float4(0.f, 0.f, 0.f, 0.f);
    for (; e + 1 < end; e += 2) {
        int2 t0 = g_csr[e];
        int2 t1 = g_csr[e + 1];
        float w0 = __int_as_float(t0.y);
        float w1 = __int_as_float(t1.y);
        float4 v0 = hp[(long)t0.x * C4 + c];
        float4 v1 = hp[(long)t1.x * C4 + c];
        acc.x += w0 * v0.x + w1 * v1.x;
        acc.y += w0 * v0.y + w1 * v1.y;
        acc.z += w0 * v0.z + w1 * v1.z;
        acc.w += w0 * v0.w + w1 * v1.w;
    }
    if (e < end) {
        int2 t0 = g_csr[e];
        float w0 = __int_as_float(t0.y);
        float4 v0 = hp[(long)t0.x * C4 + c];
        acc.x += w0 * v0.x;
        acc.y += w0 * v0.y;
        acc.z += w0 * v0.z;
        acc.w += w0 * v0.w;
    }

    if (EPI == 1) {
        float4 bb = *reinterpret_cast<const float4*>(bias + c * 4);
        acc.x = fmaxf(acc.x + bb.x, 0.f);
        acc.y = fmaxf(acc.y + bb.y, 0.f);
        acc.z = fmaxf(acc.z + bb.z, 0.f);
        acc.w = fmaxf(acc.w + bb.w, 0.f);
    }
    acc.x = rnd_tf32(acc.x);
    acc.y = rnd_tf32(acc.y);
    acc.z = rnd_tf32(acc.z);
    acc.w = rnd_tf32(acc.w);

    reinterpret_cast<float4*>(agg)[(long)n * C4 + c] = acc;
}

// =========================================================
// Fused layer-3 aggregation + bias + log_softmax.
// One warp per node: lane holds ch=lane, and ch=32+lane for lane<8.
// out[n] = log_softmax(sum_e w_e * h[src_e] + b)
// =========================================================
__global__ __launch_bounds__(256) void gather40_lsm_kernel(
    const float* __restrict__ h, const float* __restrict__ b,
    float* __restrict__ out)
{
    int n = (int)(((long)blockIdx.x * blockDim.x + threadIdx.x) >> 5);
    int lane = threadIdx.x & 31;
    if (n >= N_NODES) return;

    int e   = g_off[n];
    int end = g_off[n + 1];
    float acc0 = 0.f, acc1 = 0.f;

    for (; e + 1 < end; e += 2) {
        int2 t0 = g_csr[e];
        int2 t1 = g_csr[e + 1];
        float w0 = __int_as_float(t0.y);
        float w1 = __int_as_float(t1.y);
        const float* r0 = h + (long)t0.x * OUT_CH;
        const float* r1 = h + (long)t1.x * OUT_CH;
        acc0 += w0 * r0[lane] + w1 * r1[lane];
        if (lane < 8) acc1 += w0 * r0[32 + lane] + w1 * r1[32 + lane];
    }
    if (e < end) {
        int2 t0 = g_csr[e];
        float w0 = __int_as_float(t0.y);
        const float* r0 = h + (long)t0.x * OUT_CH;
        acc0 += w0 * r0[lane];
        if (lane < 8) acc1 += w0 * r0[32 + lane];
    }

    float v0 = acc0 + b[lane];
    float v1 = (lane < 8) ? (acc1 + b[32 + lane]) : -INFINITY;

    float m = fmaxf(v0, v1);
#pragma unroll
    for (int o = 16; o > 0; o >>= 1)
        m = fmaxf(m, __shfl_xor_sync(0xFFFFFFFFu, m, o));

    float s = __expf(v0 - m) + ((lane < 8) ? __expf(v1 - m) : 0.f);
#pragma unroll
    for (int o = 16; o > 0; o >>= 1)
        s += __shfl_xor_sync(0xFFFFFFFFu, s, o);

    float lse = m + logf(s);
    float* row = out + (long)n * OUT_CH;
    row[lane] = v0 - lse;
    if (lane < 8) row[32 + lane] = v1 - lse;
}

// ---------------------------------------------------------
// launch
// ---------------------------------------------------------
extern "C" void kernel_launch(void* const* d_in, const int* in_sizes, int n_in,
                              void* d_out, int out_size)
{
    const float* x  = (const float*)d_in[0];
    const int*   ei = (const int*)d_in[1];
    const float* ew = (const float*)d_in[2];
    const float* W1 = (const float*)d_in[3];
    const float* b1 = (const float*)d_in[4];
    const float* W2 = (const float*)d_in[5];
    const float* b2 = (const float*)d_in[6];
    const float* W3 = (const float*)d_in[7];
    const float* b3 = (const float*)d_in[8];
    float* out = (float*)d_out;

    const int* src = ei;
    const int* dst = ei + N_EDGES;

    float *buf0, *buf1, *buf2, *w1p, *w2p, *w3p;
    cudaGetSymbolAddress((void**)&buf0, g_buf0);
    cudaGetSymbolAddress((void**)&buf1, g_buf1);
    cudaGetSymbolAddress((void**)&buf2, g_buf2);
    cudaGetSymbolAddress((void**)&w1p, g_w1);
    cudaGetSymbolAddress((void**)&w2p, g_w2);
    cudaGetSymbolAddress((void**)&w3p, g_w3);

    const int mtiles = (N_NODES + GBM - 1) / GBM;   // 391
    dim3 grid_wide(HID / 128, mtiles);              // 2 x 391 (BN=128)
    dim3 grid_narrow(1, mtiles);                    // 1 x 391 (BN=64, N=40)

    // weight prep + CSR build (parallel scan)
    prep_kernel<<<(HID * HID + 255) / 256, 256>>>(W1, W2, W3);
    zero_deg_kernel<<<(N_NODES + 255) / 256, 256>>>();
    hist_kernel<<<(N_EDGES + 255) / 256, 256>>>(dst);
    scan_block_kernel<<<NSB, 256>>>();
    scan_top_kernel<<<1, 256>>>();
    scan_finalize_kernel<<<NSB, 256>>>();
    fill_kernel<<<(N_EDGES + 255) / 256, 256>>>(src, dst, ew);

    // ---- layer 1 (reordered): agg_x = A_hat @ x ; h1 = relu(agg_x @ W1 + b1) ----
    gather_kernel<32, 0><<<(N_NODES * 32 + 255) / 256, 256>>>(x, nullptr, buf1);
    gemm_tf32<1, 128><<<grid_wide, 256>>>(buf1, w1p, b1, buf0, N_NODES, HID, IN_CH);

    // ---- layer 2: h2 = h1r @ W2 ; agg2 = relu(A_hat @ h2 + b2) ----
    gemm_tf32<0, 128><<<grid_wide, 256>>>(buf0, w2p, nullptr, buf2, N_NODES, HID, HID);
    gather_kernel<64, 1><<<(N_NODES * 2 * 32 + 255) / 256, 256>>>(buf2, b2, buf1);

    // ---- layer 3: h3 = agg2r @ W3 ; out = log_softmax(A_hat @ h3 + b3) ----
    gemm_tf32<0, 64><<<grid_narrow, 256>>>(buf1, w3p, nullptr, buf0, N_NODES, OUT_CH, HID);
    gather40_lsm_kernel<<<(N_NODES * 32 + 255) / 256, 256>>>(buf0, b3, out);
}

// round 14
// speedup vs baseline: 1.0058x; 1.0058x over previous
#include <cuda_runtime.h>
#include <cuda_bf16.h>
#include <math.h>
#include <stdint.h>

// Problem constants
#define N_NODES 50000
#define N_EDGES 800000
#define IN_CH   128
#define HID     256
#define OUT_CH  40

// -------- static device scratch (allocation-free) --------
__device__ float g_buf0[(size_t)N_NODES * HID];
__device__ float g_buf1[(size_t)N_NODES * HID];
__device__ float g_buf2[(size_t)N_NODES * HID];

// tf32-rounded weights
__device__ float g_w1[IN_CH * HID];
__device__ float g_w2[HID * HID];
__device__ float g_w3[HID * OUT_CH];

// CSR-by-dst scratch (packed: .x = src, .y = float-bits of weight)
#define NSB ((N_NODES + 255) / 256)   // 196 scan blocks
__device__ int   g_deg[N_NODES];
__device__ int   g_off[N_NODES + 1];
__device__ int   g_pos[N_NODES];
__device__ int   g_bsum[NSB];
__device__ int2  g_csr[N_EDGES];

__device__ __forceinline__ float rnd_tf32(float f) {
    uint32_t r;
    asm("cvt.rna.tf32.f32 %0, %1;" : "=r"(r) : "f"(f));
    return __uint_as_float(r);
}

// =========================================================
// tf32 tensor-core GEMM: C[M,N] = A[M,K] @ B[K,N]
// A and B must be tf32-pre-rounded fp32.
// EPI: 0 = plain store, 1 = rnd_tf32(relu(acc + bias[n]))
// 512 threads = 16 warps (4M x 4N), block tile 128 x BN x 32,
// warp tile 32 x BN/4. Per-warp inner loop identical to the
// R4-proven 32x32 pattern (A k-major + XOR swizzle).
// =========================================================
#define GBM 128
#define GBK 32
#define ASTRIDE 136

__device__ __forceinline__ void mma_tf32(float* d, const uint32_t* a, const uint32_t* b) {
    asm volatile(
        "mma.sync.aligned.m16n8k8.row.col.f32.tf32.tf32.f32 "
        "{%0,%1,%2,%3}, {%4,%5,%6,%7}, {%8,%9}, {%0,%1,%2,%3};\n"
        : "+f"(d[0]), "+f"(d[1]), "+f"(d[2]), "+f"(d[3])
        : "r"(a[0]), "r"(a[1]), "r"(a[2]), "r"(a[3]),
          "r"(b[0]), "r"(b[1]));
}

template <int EPI, int BN>
__global__ __launch_bounds__(512) void gemm_tf32(
    const float* __restrict__ A, const float* __restrict__ B,
    const float* __restrict__ bias, float* __restrict__ C,
    int M, int N, int K)
{
    constexpr int BSTR   = BN + 8;         // word stride, %32 == 8
    constexpr int WN     = BN / 4;         // warp N-tile
    constexpr int NJ     = BN / 32;        // 8-col groups per warp
    constexpr int NB4    = (GBK * BN / 4) / 512;  // B float4 per thread (>=1)
    constexpr int BLANES = BN / 4;         // float4 lanes per B row

    __shared__ __align__(16) float As[GBK * ASTRIDE];
    __shared__ __align__(16) float Bs[GBK * BSTR];

    const int tid  = threadIdx.x;
    const int warp = tid >> 5;             // 0..15
    const int lane = tid & 31;
    const int bm = blockIdx.y * GBM;
    const int bn = blockIdx.x * BN;

    const int wm = (warp >> 2) * 32;       // 4 warps along M
    const int wn = (warp & 3) * WN;        // 4 warps along N
    const int qr = lane >> 2;
    const int qc = lane & 3;

    const int ar  = tid >> 3;              // A base row 0..63 (+i*64)
    const int ac4 = (tid & 7) * 4;         // A k-offset

    float acc[2][NJ][4];
#pragma unroll
    for (int i = 0; i < 2; i++)
#pragma unroll
        for (int j = 0; j < NJ; j++)
#pragma unroll
            for (int t = 0; t < 4; t++) acc[i][j][t] = 0.f;

    float4 ra[2], rb[NB4];

    // ---- preload tile k0 = 0 ----
#pragma unroll
    for (int i = 0; i < 2; i++) {
        int gr = bm + ar + i * 64;
        ra[i] = (gr < M)
            ? *reinterpret_cast<const float4*>(A + (long)gr * K + ac4)
            : make_float4(0.f, 0.f, 0.f, 0.f);
    }
#pragma unroll
    for (int i = 0; i < NB4; i++) {
        int idx  = tid + i * 512;
        int krow = idx / BLANES;
        int bc4  = (idx % BLANES) * 4;
        int gc = bn + bc4;
        float4 v = make_float4(0.f, 0.f, 0.f, 0.f);
        if (gc + 3 < N) {
            v = *reinterpret_cast<const float4*>(B + (long)krow * N + gc);
        } else {
            float* pv = &v.x;
#pragma unroll
            for (int j = 0; j < 4; j++)
                if (gc + j < N) pv[j] = B[(long)krow * N + gc + j];
        }
        rb[i] = v;
    }

    for (int k0 = 0; k0 < K; k0 += GBK) {
        // ---- store regs -> smem ----
#pragma unroll
        for (int i = 0; i < 2; i++) {
            int row = ar + i * 64;
            int sm = row ^ (((ac4 >> 2) & 7) << 3);
            const float* pv = &ra[i].x;
#pragma unroll
            for (int j = 0; j < 4; j++)
                As[(ac4 + j) * ASTRIDE + sm] = pv[j];
        }
#pragma unroll
        for (int i = 0; i < NB4; i++) {
            int idx  = tid + i * 512;
            int krow = idx / BLANES;
            int bc4  = (idx % BLANES) * 4;
            *reinterpret_cast<float4*>(&Bs[krow * BSTR + bc4]) = rb[i];
        }
        __syncthreads();

        // ---- prefetch next tile while mma runs ----
        if (k0 + GBK < K) {
            int kn = k0 + GBK;
#pragma unroll
            for (int i = 0; i < 2; i++) {
                int gr = bm + ar + i * 64;
                ra[i] = (gr < M)
                    ? *reinterpret_cast<const float4*>(A + (long)gr * K + kn + ac4)
                    : make_float4(0.f, 0.f, 0.f, 0.f);
            }
#pragma unroll
            for (int i = 0; i < NB4; i++) {
                int idx  = tid + i * 512;
                int krow = idx / BLANES;
                int bc4  = (idx % BLANES) * 4;
                int gc = bn + bc4;
                float4 v = make_float4(0.f, 0.f, 0.f, 0.f);
                if (gc + 3 < N) {
                    v = *reinterpret_cast<const float4*>(B + (long)(kn + krow) * N + gc);
                } else {
                    float* pv = &v.x;
#pragma unroll
                    for (int j = 0; j < 4; j++)
                        if (gc + j < N) pv[j] = B[(long)(kn + krow) * N + gc + j];
                }
                rb[i] = v;
            }
        }

        // ---- 4 k8-steps ----
#pragma unroll
        for (int ks = 0; ks < 4; ks++) {
            int kb = ks * 8;
            int kA0 = kb + qc;
            int kA1 = kb + qc + 4;
            int sw0 = ((kA0 >> 2) & 7) << 3;
            int sw1 = ((kA1 >> 2) & 7) << 3;

            uint32_t a[2][4];
#pragma unroll
            for (int i = 0; i < 2; i++) {
                int mb = wm + i * 16;
                a[i][0] = __float_as_uint(As[kA0 * ASTRIDE + ((mb + qr)     ^ sw0)]);
                a[i][1] = __float_as_uint(As[kA0 * ASTRIDE + ((mb + qr + 8) ^ sw0)]);
                a[i][2] = __float_as_uint(As[kA1 * ASTRIDE + ((mb + qr)     ^ sw1)]);
                a[i][3] = __float_as_uint(As[kA1 * ASTRIDE + ((mb + qr + 8) ^ sw1)]);
            }
            uint32_t b[NJ][2];
#pragma unroll
            for (int j = 0; j < NJ; j++) {
                int nb = wn + j * 8;
                b[j][0] = __float_as_uint(Bs[(kb + qc)     * BSTR + nb + qr]);
                b[j][1] = __float_as_uint(Bs[(kb + qc + 4) * BSTR + nb + qr]);
            }
#pragma unroll
            for (int i = 0; i < 2; i++)
#pragma unroll
                for (int j = 0; j < NJ; j++)
                    mma_tf32(acc[i][j], a[i], b[j]);
        }
        __syncthreads();
    }

    // ---- epilogue ----
#pragma unroll
    for (int i = 0; i < 2; i++) {
        int r0 = bm + wm + i * 16 + qr;
        int r1 = r0 + 8;
#pragma unroll
        for (int j = 0; j < NJ; j++) {
            int c0 = bn + wn + j * 8 + qc * 2;
            float v0 = acc[i][j][0], v1 = acc[i][j][1];
            float v2 = acc[i][j][2], v3 = acc[i][j][3];
            if (EPI == 1) {
                float bb0 = (c0 < N) ? bias[c0] : 0.f;
                float bb1 = (c0 + 1 < N) ? bias[c0 + 1] : 0.f;
                v0 = rnd_tf32(fmaxf(v0 + bb0, 0.f));
                v1 = rnd_tf32(fmaxf(v1 + bb1, 0.f));
                v2 = rnd_tf32(fmaxf(v2 + bb0, 0.f));
                v3 = rnd_tf32(fmaxf(v3 + bb1, 0.f));
            }
            if (r0 < M) {
                if (c0     < N) C[(long)r0 * N + c0]     = v0;
                if (c0 + 1 < N) C[(long)r0 * N + c0 + 1] = v1;
            }
            if (r1 < M) {
                if (c0     < N) C[(long)r1 * N + c0]     = v2;
                if (c0 + 1 < N) C[(long)r1 * N + c0 + 1] = v3;
            }
        }
    }
}

// =========================================================
// weight prep (tf32 round) + degree zeroing, merged
// =========================================================
__global__ void prep_kernel(const float* __restrict__ W1,
                            const float* __restrict__ W2,
                            const float* __restrict__ W3)
{
    int i = blockIdx.x * blockDim.x + threadIdx.x;
    if (i < IN_CH * HID)  g_w1[i] = rnd_tf32(W1[i]);
    if (i < HID * HID)    g_w2[i] = rnd_tf32(W2[i]);
    if (i < HID * OUT_CH) g_w3[i] = rnd_tf32(W3[i]);
    if (i < N_NODES)      g_deg[i] = 0;
}

// =========================================================
// CSR build: hist -> block scan -> finalize(+top scan) -> fill
// =========================================================
__global__ void hist_kernel(const int* __restrict__ dst)
{
    int e = blockIdx.x * blockDim.x + threadIdx.x;
    if (e < N_EDGES) atomicAdd(&g_deg[dst[e]], 1);
}

__global__ __launch_bounds__(256) void scan_block_kernel()
{
    __shared__ int s[256];
    int t = threadIdx.x;
    int i = blockIdx.x * 256 + t;
    int v = (i < N_NODES) ? g_deg[i] : 0;
    s[t] = v;
    __syncthreads();
#pragma unroll
    for (int o = 1; o < 256; o <<= 1) {
        int add = (t >= o) ? s[t - o] : 0;
        __syncthreads();
        s[t] += add;
        __syncthreads();
    }
    if (i < N_NODES) g_off[i] = s[t] - v;          // block-local exclusive
    if (t == 255) g_bsum[blockIdx.x] = s[255];
}

// Merged top-scan + finalize: every block redundantly scans the 196
// block sums in smem, picks its own exclusive prefix, applies it.
__global__ __launch_bounds__(256) void scan_finalize_kernel()
{
    __shared__ int s[256];
    int t = threadIdx.x;
    int v = (t < NSB) ? g_bsum[t] : 0;
    s[t] = v;
    __syncthreads();
#pragma unroll
    for (int o = 1; o < 256; o <<= 1) {
        int add = (t >= o) ? s[t - o] : 0;
        __syncthreads();
        s[t] += add;
        __syncthreads();
    }
    int boff = s[blockIdx.x] - g_bsum[blockIdx.x];  // exclusive prefix of this block
    int i = blockIdx.x * 256 + t;
    if (i < N_NODES) {
        int o = g_off[i] + boff;
        g_off[i] = o;
        g_pos[i] = o;
    }
    if (i == 0) g_off[N_NODES] = N_EDGES;
}

__global__ void fill_kernel(const int* __restrict__ src,
                            const int* __restrict__ dst,
                            const float* __restrict__ ew)
{
    int e = blockIdx.x * blockDim.x + threadIdx.x;
    if (e >= N_EDGES) return;
    int p = atomicAdd(&g_pos[dst[e]], 1);
    g_csr[p] = make_int2(src[e], __float_as_int(ew[e]));
}

// =========================================================
// CSR gather: agg[n] = sum_{e} w_e * h[src_e]
// EPI: 0 = rnd_tf32(acc), 1 = rnd_tf32(relu(acc + bias[ch]))
// =========================================================
template <int C4, int EPI>
__global__ __launch_bounds__(256) void gather_kernel(
    const float* __restrict__ h, const float* __restrict__ bias,
    float* __restrict__ agg)
{
    const int SLICES = C4 / 32;
    int gw = (int)(((long)blockIdx.x * blockDim.x + threadIdx.x) >> 5);
    int lane = threadIdx.x & 31;
    int n = gw / SLICES;
    int sl = gw - n * SLICES;
    if (n >= N_NODES) return;
    int c = sl * 32 + lane;

    const float4* hp = reinterpret_cast<const float4*>(h);
    int e   = g_off[n];
    int end = g_off[n + 1];

    float4 acc = make_float4(0.f, 0.f, 0.f, 0.f);
    for (; e + 1 < end; e += 2) {
        int2 t0 = g_csr[e];
        int2 t1 = g_csr[e + 1];
        float w0 = __int_as_float(t0.y);
        float w1 = __int_as_float(t1.y);
        float4 v0 = hp[(long)t0.x * C4 + c];
        float4 v1 = hp[(long)t1.x * C4 + c];
        acc.x += w0 * v0.x + w1 * v1.x;
        acc.y += w0 * v0.y + w1 * v1.y;
        acc.z += w0 * v0.z + w1 * v1.z;
        acc.w += w0 * v0.w + w1 * v1.w;
    }
    if (e < end) {
        int2 t0 = g_csr[e];
        float w0 = __int_as_float(t0.y);
        float4 v0 = hp[(long)t0.x * C4 + c];
        acc.x += w0 * v0.x;
        acc.y += w0 * v0.y;
        acc.z += w0 * v0.z;
        acc.w += w0 * v0.w;
    }

    if (EPI == 1) {
        float4 bb = *reinterpret_cast<const float4*>(bias + c * 4);
        acc.x = fmaxf(acc.x + bb.x, 0.f);
        acc.y = fmaxf(acc.y + bb.y, 0.f);
        acc.z = fmaxf(acc.z + bb.z, 0.f);
        acc.w = fmaxf(acc.w + bb.w, 0.f);
    }
    acc.x = rnd_tf32(acc.x);
    acc.y = rnd_tf32(acc.y);
    acc.z = rnd_tf32(acc.z);
    acc.w = rnd_tf32(acc.w);

    reinterpret_cast<float4*>(agg)[(long)n * C4 + c] = acc;
}

// =========================================================
// Fused layer-3 aggregation + bias + log_softmax.
// One warp per node: lane holds ch=lane, and ch=32+lane for lane<8.
// =========================================================
__global__ __launch_bounds__(256) void gather40_lsm_kernel(
    const float* __restrict__ h, const float* __restrict__ b,
    float* __restrict__ out)
{
    int n = (int)(((long)blockIdx.x * blockDim.x + threadIdx.x) >> 5);
    int lane = threadIdx.x & 31;
    if (n >= N_NODES) return;

    int e   = g_off[n];
    int end = g_off[n + 1];
    float acc0 = 0.f, acc1 = 0.f;

    for (; e + 1 < end; e += 2) {
        int2 t0 = g_csr[e];
        int2 t1 = g_csr[e + 1];
        float w0 = __int_as_float(t0.y);
        float w1 = __int_as_float(t1.y);
        const float* r0 = h + (long)t0.x * OUT_CH;
        const float* r1 = h + (long)t1.x * OUT_CH;
        acc0 += w0 * r0[lane] + w1 * r1[lane];
        if (lane < 8) acc1 += w0 * r0[32 + lane] + w1 * r1[32 + lane];
    }
    if (e < end) {
        int2 t0 = g_csr[e];
        float w0 = __int_as_float(t0.y);
        const float* r0 = h + (long)t0.x * OUT_CH;
        acc0 += w0 * r0[lane];
        if (lane < 8) acc1 += w0 * r0[32 + lane];
    }

    float v0 = acc0 + b[lane];
    float v1 = (lane < 8) ? (acc1 + b[32 + lane]) : -INFINITY;

    float m = fmaxf(v0, v1);
#pragma unroll
    for (int o = 16; o > 0; o >>= 1)
        m = fmaxf(m, __shfl_xor_sync(0xFFFFFFFFu, m, o));

    float s = __expf(v0 - m) + ((lane < 8) ? __expf(v1 - m) : 0.f);
#pragma unroll
    for (int o = 16; o > 0; o >>= 1)
        s += __shfl_xor_sync(0xFFFFFFFFu, s, o);

    float lse = m + logf(s);
    float* row = out + (long)n * OUT_CH;
    row[lane] = v0 - lse;
    if (lane < 8) row[32 + lane] = v1 - lse;
}

// ---------------------------------------------------------
// launch
// ---------------------------------------------------------
extern "C" void kernel_launch(void* const* d_in, const int* in_sizes, int n_in,
                              void* d_out, int out_size)
{
    const float* x  = (const float*)d_in[0];
    const int*   ei = (const int*)d_in[1];
    const float* ew = (const float*)d_in[2];
    const float* W1 = (const float*)d_in[3];
    const float* b1 = (const float*)d_in[4];
    const float* W2 = (const float*)d_in[5];
    const float* b2 = (const float*)d_in[6];
    const float* W3 = (const float*)d_in[7];
    const float* b3 = (const float*)d_in[8];
    float* out = (float*)d_out;

    const int* src = ei;
    const int* dst = ei + N_EDGES;

    float *buf0, *buf1, *buf2, *w1p, *w2p, *w3p;
    cudaGetSymbolAddress((void**)&buf0, g_buf0);
    cudaGetSymbolAddress((void**)&buf1, g_buf1);
    cudaGetSymbolAddress((void**)&buf2, g_buf2);
    cudaGetSymbolAddress((void**)&w1p, g_w1);
    cudaGetSymbolAddress((void**)&w2p, g_w2);
    cudaGetSymbolAddress((void**)&w3p, g_w3);

    const int mtiles = (N_NODES + GBM - 1) / GBM;   // 391
    dim3 grid_wide(HID / 128, mtiles);              // 2 x 391 (BN=128)
    dim3 grid_narrow(1, mtiles);                    // 1 x 391 (BN=64, N=40)

    // weight prep (+deg zero) + CSR build
    prep_kernel<<<(HID * HID + 255) / 256, 256>>>(W1, W2, W3);
    hist_kernel<<<(N_EDGES + 255) / 256, 256>>>(dst);
    scan_block_kernel<<<NSB, 256>>>();
    scan_finalize_kernel<<<NSB, 256>>>();
    fill_kernel<<<(N_EDGES + 255) / 256, 256>>>(src, dst, ew);

    // ---- layer 1 (reordered): agg_x = A_hat @ x ; h1 = relu(agg_x @ W1 + b1) ----
    gather_kernel<32, 0><<<(N_NODES * 32 + 255) / 256, 256>>>(x, nullptr, buf1);
    gemm_tf32<1, 128><<<grid_wide, 512>>>(buf1, w1p, b1, buf0, N_NODES, HID, IN_CH);

    // ---- layer 2: h2 = h1r @ W2 ; agg2 = relu(A_hat @ h2 + b2) ----
    gemm_tf32<0, 128><<<grid_wide, 512>>>(buf0, w2p, nullptr, buf2, N_NODES, HID, HID);
    gather_kernel<64, 1><<<(N_NODES * 2 * 32 + 255) / 256, 256>>>(buf2, b2, buf1);

    // ---- layer 3: h3 = agg2r @ W3 ; out = log_softmax(A_hat @ h3 + b3) ----
    gemm_tf32<0, 64><<<grid_narrow, 512>>>(buf1, w3p, nullptr, buf0, N_NODES, OUT_CH, HID);
    gather40_lsm_kernel<<<(N_NODES * 32 + 255) / 256, 256>>>(buf0, b3, out);
}

// round 15
// speedup vs baseline: 1.0068x; 1.0010x over previous
#include <cuda_runtime.h>
#include <cuda_bf16.h>
#include <math.h>
#include <stdint.h>

// Problem constants
#define N_NODES 50000
#define N_EDGES 800000
#define IN_CH   128
#define HID     256
#define OUT_CH  40

// -------- static device scratch (allocation-free) --------
__device__ float g_buf0[(size_t)N_NODES * HID];
__device__ float g_buf1[(size_t)N_NODES * HID];
__device__ float g_buf2[(size_t)N_NODES * HID];

// tf32-rounded weights
__device__ float g_w1[IN_CH * HID];
__device__ float g_w2[HID * HID];
__device__ float g_w3[HID * OUT_CH];

// CSR-by-dst scratch (packed: .x = src, .y = float-bits of weight)
#define NSB ((N_NODES + 255) / 256)   // 196 scan blocks
__device__ int   g_deg[N_NODES];
__device__ int   g_off[N_NODES + 1];
__device__ int   g_pos[N_NODES];
__device__ int   g_bsum[NSB];
__device__ int2  g_csr[N_EDGES];

__device__ __forceinline__ float rnd_tf32(float f) {
    uint32_t r;
    asm("cvt.rna.tf32.f32 %0, %1;" : "=r"(r) : "f"(f));
    return __uint_as_float(r);
}

// =========================================================
// tf32 tensor-core GEMM: C[M,N] = A[M,K] @ B[K,N]
// A and B must be tf32-pre-rounded fp32.
// EPI: 0 = plain store, 1 = rnd_tf32(relu(acc + bias[n]))
// 512 threads = 16 warps (4M x 4N), block tile 128 x BN x 32,
// warp tile 32 x BN/4. Per-warp inner loop identical to the
// R4-proven 32x32 pattern (A k-major + XOR swizzle).
// =========================================================
#define GBM 128
#define GBK 32
#define ASTRIDE 136

__device__ __forceinline__ void mma_tf32(float* d, const uint32_t* a, const uint32_t* b) {
    asm volatile(
        "mma.sync.aligned.m16n8k8.row.col.f32.tf32.tf32.f32 "
        "{%0,%1,%2,%3}, {%4,%5,%6,%7}, {%8,%9}, {%0,%1,%2,%3};\n"
        : "+f"(d[0]), "+f"(d[1]), "+f"(d[2]), "+f"(d[3])
        : "r"(a[0]), "r"(a[1]), "r"(a[2]), "r"(a[3]),
          "r"(b[0]), "r"(b[1]));
}

template <int EPI, int BN>
__global__ __launch_bounds__(512) void gemm_tf32(
    const float* __restrict__ A, const float* __restrict__ B,
    const float* __restrict__ bias, float* __restrict__ C,
    int M, int N, int K)
{
    constexpr int BSTR   = BN + 8;         // word stride, %32 == 8
    constexpr int WN     = BN / 4;         // warp N-tile
    constexpr int NJ     = BN / 32;        // 8-col groups per warp
    constexpr int NB4    = (GBK * BN / 4) / 512;  // B float4 per thread (>=1)
    constexpr int BLANES = BN / 4;         // float4 lanes per B row

    __shared__ __align__(16) float As[GBK * ASTRIDE];
    __shared__ __align__(16) float Bs[GBK * BSTR];

    const int tid  = threadIdx.x;
    const int warp = tid >> 5;             // 0..15
    const int lane = tid & 31;
    const int bm = blockIdx.y * GBM;
    const int bn = blockIdx.x * BN;

    const int wm = (warp >> 2) * 32;       // 4 warps along M
    const int wn = (warp & 3) * WN;        // 4 warps along N
    const int qr = lane >> 2;
    const int qc = lane & 3;

    const int ar  = tid >> 3;              // A base row 0..63 (+i*64)
    const int ac4 = (tid & 7) * 4;         // A k-offset

    float acc[2][NJ][4];
#pragma unroll
    for (int i = 0; i < 2; i++)
#pragma unroll
        for (int j = 0; j < NJ; j++)
#pragma unroll
            for (int t = 0; t < 4; t++) acc[i][j][t] = 0.f;

    float4 ra[2], rb[NB4];

    // ---- preload tile k0 = 0 ----
#pragma unroll
    for (int i = 0; i < 2; i++) {
        int gr = bm + ar + i * 64;
        ra[i] = (gr < M)
            ? *reinterpret_cast<const float4*>(A + (long)gr * K + ac4)
            : make_float4(0.f, 0.f, 0.f, 0.f);
    }
#pragma unroll
    for (int i = 0; i < NB4; i++) {
        int idx  = tid + i * 512;
        int krow = idx / BLANES;
        int bc4  = (idx % BLANES) * 4;
        int gc = bn + bc4;
        float4 v = make_float4(0.f, 0.f, 0.f, 0.f);
        if (gc + 3 < N) {
            v = *reinterpret_cast<const float4*>(B + (long)krow * N + gc);
        } else {
            float* pv = &v.x;
#pragma unroll
            for (int j = 0; j < 4; j++)
                if (gc + j < N) pv[j] = B[(long)krow * N + gc + j];
        }
        rb[i] = v;
    }

    for (int k0 = 0; k0 < K; k0 += GBK) {
        // ---- store regs -> smem ----
#pragma unroll
        for (int i = 0; i < 2; i++) {
            int row = ar + i * 64;
            int sm = row ^ (((ac4 >> 2) & 7) << 3);
            const float* pv = &ra[i].x;
#pragma unroll
            for (int j = 0; j < 4; j++)
                As[(ac4 + j) * ASTRIDE + sm] = pv[j];
        }
#pragma unroll
        for (int i = 0; i < NB4; i++) {
            int idx  = tid + i * 512;
            int krow = idx / BLANES;
            int bc4  = (idx % BLANES) * 4;
            *reinterpret_cast<float4*>(&Bs[krow * BSTR + bc4]) = rb[i];
        }
        __syncthreads();

        // ---- prefetch next tile while mma runs ----
        if (k0 + GBK < K) {
            int kn = k0 + GBK;
#pragma unroll
            for (int i = 0; i < 2; i++) {
                int gr = bm + ar + i * 64;
                ra[i] = (gr < M)
                    ? *reinterpret_cast<const float4*>(A + (long)gr * K + kn + ac4)
                    : make_float4(0.f, 0.f, 0.f, 0.f);
            }
#pragma unroll
            for (int i = 0; i < NB4; i++) {
                int idx  = tid + i * 512;
                int krow = idx / BLANES;
                int bc4  = (idx % BLANES) * 4;
                int gc = bn + bc4;
                float4 v = make_float4(0.f, 0.f, 0.f, 0.f);
                if (gc + 3 < N) {
                    v = *reinterpret_cast<const float4*>(B + (long)(kn + krow) * N + gc);
                } else {
                    float* pv = &v.x;
#pragma unroll
                    for (int j = 0; j < 4; j++)
                        if (gc + j < N) pv[j] = B[(long)(kn + krow) * N + gc + j];
                }
                rb[i] = v;
            }
        }

        // ---- 4 k8-steps ----
#pragma unroll
        for (int ks = 0; ks < 4; ks++) {
            int kb = ks * 8;
            int kA0 = kb + qc;
            int kA1 = kb + qc + 4;
            int sw0 = ((kA0 >> 2) & 7) << 3;
            int sw1 = ((kA1 >> 2) & 7) << 3;

            uint32_t a[2][4];
#pragma unroll
            for (int i = 0; i < 2; i++) {
                int mb = wm + i * 16;
                a[i][0] = __float_as_uint(As[kA0 * ASTRIDE + ((mb + qr)     ^ sw0)]);
                a[i][1] = __float_as_uint(As[kA0 * ASTRIDE + ((mb + qr + 8) ^ sw0)]);
                a[i][2] = __float_as_uint(As[kA1 * ASTRIDE + ((mb + qr)     ^ sw1)]);
                a[i][3] = __float_as_uint(As[kA1 * ASTRIDE + ((mb + qr + 8) ^ sw1)]);
            }
            uint32_t b[NJ][2];
#pragma unroll
            for (int j = 0; j < NJ; j++) {
                int nb = wn + j * 8;
                b[j][0] = __float_as_uint(Bs[(kb + qc)     * BSTR + nb + qr]);
                b[j][1] = __float_as_uint(Bs[(kb + qc + 4) * BSTR + nb + qr]);
            }
#pragma unroll
            for (int i = 0; i < 2; i++)
#pragma unroll
                for (int j = 0; j < NJ; j++)
                    mma_tf32(acc[i][j], a[i], b[j]);
        }
        __syncthreads();
    }

    // ---- epilogue ----
#pragma unroll
    for (int i = 0; i < 2; i++) {
        int r0 = bm + wm + i * 16 + qr;
        int r1 = r0 + 8;
#pragma unroll
        for (int j = 0; j < NJ; j++) {
            int c0 = bn + wn + j * 8 + qc * 2;
            float v0 = acc[i][j][0], v1 = acc[i][j][1];
            float v2 = acc[i][j][2], v3 = acc[i][j][3];
            if (EPI == 1) {
                float bb0 = (c0 < N) ? bias[c0] : 0.f;
                float bb1 = (c0 + 1 < N) ? bias[c0 + 1] : 0.f;
                v0 = rnd_tf32(fmaxf(v0 + bb0, 0.f));
                v1 = rnd_tf32(fmaxf(v1 + bb1, 0.f));
                v2 = rnd_tf32(fmaxf(v2 + bb0, 0.f));
                v3 = rnd_tf32(fmaxf(v3 + bb1, 0.f));
            }
            if (r0 < M) {
                if (c0     < N) C[(long)r0 * N + c0]     = v0;
                if (c0 + 1 < N) C[(long)r0 * N + c0 + 1] = v1;
            }
            if (r1 < M) {
                if (c0     < N) C[(long)r1 * N + c0]     = v2;
                if (c0 + 1 < N) C[(long)r1 * N + c0 + 1] = v3;
            }
        }
    }
}

// =========================================================
// weight prep (tf32 round) + degree zeroing, merged
// =========================================================
__global__ void prep_kernel(const float* __restrict__ W1,
                            const float* __restrict__ W2,
                            const float* __restrict__ W3)
{
    int i = blockIdx.x * blockDim.x + threadIdx.x;
    if (i < IN_CH * HID)  g_w1[i] = rnd_tf32(W1[i]);
    if (i < HID * HID)    g_w2[i] = rnd_tf32(W2[i]);
    if (i < HID * OUT_CH) g_w3[i] = rnd_tf32(W3[i]);
    if (i < N_NODES)      g_deg[i] = 0;
}

// =========================================================
// CSR build: hist -> block scan -> finalize(+top scan) -> fill
// =========================================================
__global__ void hist_kernel(const int* __restrict__ dst)
{
    int e = blockIdx.x * blockDim.x + threadIdx.x;
    if (e < N_EDGES) atomicAdd(&g_deg[dst[e]], 1);
}

__global__ __launch_bounds__(256) void scan_block_kernel()
{
    __shared__ int s[256];
    int t = threadIdx.x;
    int i = blockIdx.x * 256 + t;
    int v = (i < N_NODES) ? g_deg[i] : 0;
    s[t] = v;
    __syncthreads();
#pragma unroll
    for (int o = 1; o < 256; o <<= 1) {
        int add = (t >= o) ? s[t - o] : 0;
        __syncthreads();
        s[t] += add;
        __syncthreads();
    }
    if (i < N_NODES) g_off[i] = s[t] - v;          // block-local exclusive
    if (t == 255) g_bsum[blockIdx.x] = s[255];
}

// Merged top-scan + finalize: every block redundantly scans the 196
// block sums in smem, picks its own exclusive prefix, applies it.
__global__ __launch_bounds__(256) void scan_finalize_kernel()
{
    __shared__ int s[256];
    int t = threadIdx.x;
    int v = (t < NSB) ? g_bsum[t] : 0;
    s[t] = v;
    __syncthreads();
#pragma unroll
    for (int o = 1; o < 256; o <<= 1) {
        int add = (t >= o) ? s[t - o] : 0;
        __syncthreads();
        s[t] += add;
        __syncthreads();
    }
    int boff = s[blockIdx.x] - g_bsum[blockIdx.x];  // exclusive prefix of this block
    int i = blockIdx.x * 256 + t;
    if (i < N_NODES) {
        int o = g_off[i] + boff;
        g_off[i] = o;
        g_pos[i] = o;
    }
    if (i == 0) g_off[N_NODES] = N_EDGES;
}

__global__ void fill_kernel(const int* __restrict__ src,
                            const int* __restrict__ dst,
                            const float* __restrict__ ew)
{
    int e = blockIdx.x * blockDim.x + threadIdx.x;
    if (e >= N_EDGES) return;
    int p = atomicAdd(&g_pos[dst[e]], 1);
    g_csr[p] = make_int2(src[e], __float_as_int(ew[e]));
}

// =========================================================
// CSR gather: agg[n] = sum_{e} w_e * h[src_e]
// EPI: 0 = rnd_tf32(acc), 1 = rnd_tf32(relu(acc + bias[ch]))
// =========================================================
template <int C4, int EPI>
__global__ __launch_bounds__(256) void gather_kernel(
    const float* __restrict__ h, const float* __restrict__ bias,
    float* __restrict__ agg)
{
    const int SLICES = C4 / 32;
    int gw = (int)(((long)blockIdx.x * blockDim.x + threadIdx.x) >> 5);
    int lane = threadIdx.x & 31;
    int n = gw / SLICES;
    int sl = gw - n * SLICES;
    if (n >= N_NODES) return;
    int c = sl * 32 + lane;

    const float4* hp = reinterpret_cast<const float4*>(h);
    int e   = g_off[n];
    int end = g_off[n + 1];

    float4 acc = make_float4(0.f, 0.f, 0.f, 0.f);
    for (; e + 1 < end; e += 2) {
        int2 t0 = g_csr[e];
        int2 t1 = g_csr[e + 1];
        float w0 = __int_as_float(t0.y);
        float w1 = __int_as_float(t1.y);
        float4 v0 = hp[(long)t0.x * C4 + c];
        float4 v1 = hp[(long)t1.x * C4 + c];
        acc.x += w0 * v0.x + w1 * v1.x;
        acc.y += w0 * v0.y + w1 * v1.y;
        acc.z += w0 * v0.z + w1 * v1.z;
        acc.w += w0 * v0.w + w1 * v1.w;
    }
    if (e < end) {
        int2 t0 = g_csr[e];
        float w0 = __int_as_float(t0.y);
        float4 v0 = hp[(long)t0.x * C4 + c];
        acc.x += w0 * v0.x;
        acc.y += w0 * v0.y;
        acc.z += w0 * v0.z;
        acc.w += w0 * v0.w;
    }

    if (EPI == 1) {
        float4 bb = *reinterpret_cast<const float4*>(bias + c * 4);
        acc.x = fmaxf(acc.x + bb.x, 0.f);
        acc.y = fmaxf(acc.y + bb.y, 0.f);
        acc.z = fmaxf(acc.z + bb.z, 0.f);
        acc.w = fmaxf(acc.w + bb.w, 0.f);
    }
    acc.x = rnd_tf32(acc.x);
    acc.y = rnd_tf32(acc.y);
    acc.z = rnd_tf32(acc.z);
    acc.w = rnd_tf32(acc.w);

    reinterpret_cast<float4*>(agg)[(long)n * C4 + c] = acc;
}

// =========================================================
// Fused layer-3 aggregation + bias + log_softmax.
// One warp per node: lane holds ch=lane, and ch=32+lane for lane<8.
// =========================================================
__global__ __launch_bounds__(256) void gather40_lsm_kernel(
    const float* __restrict__ h, const float* __restrict__ b,
    float* __restrict__ out)
{
    int n = (int)(((long)blockIdx.x * blockDim.x + threadIdx.x) >> 5);
    int lane = threadIdx.x & 31;
    if (n >= N_NODES) return;

    int e   = g_off[n];
    int end = g_off[n + 1];
    float acc0 = 0.f, acc1 = 0.f;

    for (; e + 1 < end; e += 2) {
        int2 t0 = g_csr[e];
        int2 t1 = g_csr[e + 1];
        float w0 = __int_as_float(t0.y);
        float w1 = __int_as_float(t1.y);
        const float* r0 = h + (long)t0.x * OUT_CH;
        const float* r1 = h + (long)t1.x * OUT_CH;
        acc0 += w0 * r0[lane] + w1 * r1[lane];
        if (lane < 8) acc1 += w0 * r0[32 + lane] + w1 * r1[32 + lane];
    }
    if (e < end) {
        int2 t0 = g_csr[e];
        float w0 = __int_as_float(t0.y);
        const float* r0 = h + (long)t0.x * OUT_CH;
        acc0 += w0 * r0[lane];
        if (lane < 8) acc1 += w0 * r0[32 + lane];
    }

    float v0 = acc0 + b[lane];
    float v1 = (lane < 8) ? (acc1 + b[32 + lane]) : -INFINITY;

    float m = fmaxf(v0, v1);
#pragma unroll
    for (int o = 16; o > 0; o >>= 1)
        m = fmaxf(m, __shfl_xor_sync(0xFFFFFFFFu, m, o));

    float s = __expf(v0 - m) + ((lane < 8) ? __expf(v1 - m) : 0.f);
#pragma unroll
    for (int o = 16; o > 0; o >>= 1)
        s += __shfl_xor_sync(0xFFFFFFFFu, s, o);

    float lse = m + logf(s);
    float* row = out + (long)n * OUT_CH;
    row[lane] = v0 - lse;
    if (lane < 8) row[32 + lane] = v1 - lse;
}

// ---------------------------------------------------------
// launch
// ---------------------------------------------------------
extern "C" void kernel_launch(void* const* d_in, const int* in_sizes, int n_in,
                              void* d_out, int out_size)
{
    const float* x  = (const float*)d_in[0];
    const int*   ei = (const int*)d_in[1];
    const float* ew = (const float*)d_in[2];
    const float* W1 = (const float*)d_in[3];
    const float* b1 = (const float*)d_in[4];
    const float* W2 = (const float*)d_in[5];
    const float* b2 = (const float*)d_in[6];
    const float* W3 = (const float*)d_in[7];
    const float* b3 = (const float*)d_in[8];
    float* out = (float*)d_out;

    const int* src = ei;
    const int* dst = ei + N_EDGES;

    float *buf0, *buf1, *buf2, *w1p, *w2p, *w3p;
    cudaGetSymbolAddress((void**)&buf0, g_buf0);
    cudaGetSymbolAddress((void**)&buf1, g_buf1);
    cudaGetSymbolAddress((void**)&buf2, g_buf2);
    cudaGetSymbolAddress((void**)&w1p, g_w1);
    cudaGetSymbolAddress((void**)&w2p, g_w2);
    cudaGetSymbolAddress((void**)&w3p, g_w3);

    const int mtiles = (N_NODES + GBM - 1) / GBM;   // 391
    dim3 grid_wide(HID / 128, mtiles);              // 2 x 391 (BN=128)
    dim3 grid_narrow(1, mtiles);                    // 1 x 391 (BN=64, N=40)

    // weight prep (+deg zero) + CSR build
    prep_kernel<<<(HID * HID + 255) / 256, 256>>>(W1, W2, W3);
    hist_kernel<<<(N_EDGES + 255) / 256, 256>>>(dst);
    scan_block_kernel<<<NSB, 256>>>();
    scan_finalize_kernel<<<NSB, 256>>>();
    fill_kernel<<<(N_EDGES + 255) / 256, 256>>>(src, dst, ew);

    // ---- layer 1 (reordered): agg_x = A_hat @ x ; h1 = relu(agg_x @ W1 + b1) ----
    gather_kernel<32, 0><<<(N_NODES * 32 + 255) / 256, 256>>>(x, nullptr, buf1);
    gemm_tf32<1, 128><<<grid_wide, 512>>>(buf1, w1p, b1, buf0, N_NODES, HID, IN_CH);

    // ---- layer 2: h2 = h1r @ W2 ; agg2 = relu(A_hat @ h2 + b2) ----
    gemm_tf32<0, 128><<<grid_wide, 512>>>(buf0, w2p, nullptr, buf2, N_NODES, HID, HID);
    gather_kernel<64, 1><<<(N_NODES * 2 * 32 + 255) / 256, 256>>>(buf2, b2, buf1);

    // ---- layer 3: h3 = agg2r @ W3 ; out = log_softmax(A_hat @ h3 + b3) ----
    gemm_tf32<0, 64><<<grid_narrow, 512>>>(buf1, w3p, nullptr, buf0, N_NODES, OUT_CH, HID);
    gather40_lsm_kernel<<<(N_NODES * 32 + 255) / 256, 256>>>(buf0, b3, out);
}

// round 16
// speedup vs baseline: 1.1335x; 1.1259x over previous
#include <cuda_runtime.h>
#include <cuda_bf16.h>
#include <cuda_fp16.h>
#include <math.h>
#include <stdint.h>

// Problem constants
#define N_NODES 50000
#define N_EDGES 800000
#define IN_CH   128
#define HID     256
#define OUT_CH  40

// -------- static device scratch (allocation-free) --------
__device__ float g_buf0[(size_t)N_NODES * HID];
__device__ float g_buf1[(size_t)N_NODES * HID];

// fp16 feature buffers
__device__ __half g_h16a[(size_t)N_NODES * HID];    // x16 (128ch), later h2 (256ch)
__device__ __half g_h16b[(size_t)N_NODES * OUT_CH]; // h3 (40ch)

// tf32-rounded weights
__device__ float g_w1[IN_CH * HID];
__device__ float g_w2[HID * HID];
__device__ float g_w3[HID * OUT_CH];

// CSR-by-dst scratch (packed: .x = src, .y = float-bits of weight)
#define NSB ((N_NODES + 255) / 256)   // 196 scan blocks
__device__ int   g_deg[N_NODES];
__device__ int   g_off[N_NODES + 1];
__device__ int   g_pos[N_NODES];
__device__ int   g_bsum[NSB];
__device__ int2  g_csr[N_EDGES];

__device__ __forceinline__ float rnd_tf32(float f) {
    uint32_t r;
    asm("cvt.rna.tf32.f32 %0, %1;" : "=r"(r) : "f"(f));
    return __uint_as_float(r);
}

// =========================================================
// tf32 tensor-core GEMM: C[M,N] = A[M,K] @ B[K,N]
// A and B must be tf32-pre-rounded fp32.
// EPI: 0 = plain fp32 store
//      1 = rnd_tf32(relu(acc + bias[n])) fp32 store
//      2 = fp16 store (C interpreted as __half*)
// 512 threads = 16 warps (4M x 4N), block tile 128 x BN x 32.
// =========================================================
#define GBM 128
#define GBK 32
#define ASTRIDE 136

__device__ __forceinline__ void mma_tf32(float* d, const uint32_t* a, const uint32_t* b) {
    asm volatile(
        "mma.sync.aligned.m16n8k8.row.col.f32.tf32.tf32.f32 "
        "{%0,%1,%2,%3}, {%4,%5,%6,%7}, {%8,%9}, {%0,%1,%2,%3};\n"
        : "+f"(d[0]), "+f"(d[1]), "+f"(d[2]), "+f"(d[3])
        : "r"(a[0]), "r"(a[1]), "r"(a[2]), "r"(a[3]),
          "r"(b[0]), "r"(b[1]));
}

template <int EPI, int BN>
__global__ __launch_bounds__(512) void gemm_tf32(
    const float* __restrict__ A, const float* __restrict__ B,
    const float* __restrict__ bias, float* __restrict__ C,
    int M, int N, int K)
{
    constexpr int BSTR   = BN + 8;
    constexpr int WN     = BN / 4;
    constexpr int NJ     = BN / 32;
    constexpr int NB4    = (GBK * BN / 4) / 512;
    constexpr int BLANES = BN / 4;

    __shared__ __align__(16) float As[GBK * ASTRIDE];
    __shared__ __align__(16) float Bs[GBK * BSTR];

    const int tid  = threadIdx.x;
    const int warp = tid >> 5;
    const int lane = tid & 31;
    const int bm = blockIdx.y * GBM;
    const int bn = blockIdx.x * BN;

    const int wm = (warp >> 2) * 32;
    const int wn = (warp & 3) * WN;
    const int qr = lane >> 2;
    const int qc = lane & 3;

    const int ar  = tid >> 3;
    const int ac4 = (tid & 7) * 4;

    float acc[2][NJ][4];
#pragma unroll
    for (int i = 0; i < 2; i++)
#pragma unroll
        for (int j = 0; j < NJ; j++)
#pragma unroll
            for (int t = 0; t < 4; t++) acc[i][j][t] = 0.f;

    float4 ra[2], rb[NB4];

    // ---- preload tile k0 = 0 ----
#pragma unroll
    for (int i = 0; i < 2; i++) {
        int gr = bm + ar + i * 64;
        ra[i] = (gr < M)
            ? *reinterpret_cast<const float4*>(A + (long)gr * K + ac4)
            : make_float4(0.f, 0.f, 0.f, 0.f);
    }
#pragma unroll
    for (int i = 0; i < NB4; i++) {
        int idx  = tid + i * 512;
        int krow = idx / BLANES;
        int bc4  = (idx % BLANES) * 4;
        int gc = bn + bc4;
        float4 v = make_float4(0.f, 0.f, 0.f, 0.f);
        if (gc + 3 < N) {
            v = *reinterpret_cast<const float4*>(B + (long)krow * N + gc);
        } else {
            float* pv = &v.x;
#pragma unroll
            for (int j = 0; j < 4; j++)
                if (gc + j < N) pv[j] = B[(long)krow * N + gc + j];
        }
        rb[i] = v;
    }

    for (int k0 = 0; k0 < K; k0 += GBK) {
        // ---- store regs -> smem ----
#pragma unroll
        for (int i = 0; i < 2; i++) {
            int row = ar + i * 64;
            int sm = row ^ (((ac4 >> 2) & 7) << 3);
            const float* pv = &ra[i].x;
#pragma unroll
            for (int j = 0; j < 4; j++)
                As[(ac4 + j) * ASTRIDE + sm] = pv[j];
        }
#pragma unroll
        for (int i = 0; i < NB4; i++) {
            int idx  = tid + i * 512;
            int krow = idx / BLANES;
            int bc4  = (idx % BLANES) * 4;
            *reinterpret_cast<float4*>(&Bs[krow * BSTR + bc4]) = rb[i];
        }
        __syncthreads();

        // ---- prefetch next tile while mma runs ----
        if (k0 + GBK < K) {
            int kn = k0 + GBK;
#pragma unroll
            for (int i = 0; i < 2; i++) {
                int gr = bm + ar + i * 64;
                ra[i] = (gr < M)
                    ? *reinterpret_cast<const float4*>(A + (long)gr * K + kn + ac4)
                    : make_float4(0.f, 0.f, 0.f, 0.f);
            }
#pragma unroll
            for (int i = 0; i < NB4; i++) {
                int idx  = tid + i * 512;
                int krow = idx / BLANES;
                int bc4  = (idx % BLANES) * 4;
                int gc = bn + bc4;
                float4 v = make_float4(0.f, 0.f, 0.f, 0.f);
                if (gc + 3 < N) {
                    v = *reinterpret_cast<const float4*>(B + (long)(kn + krow) * N + gc);
                } else {
                    float* pv = &v.x;
#pragma unroll
                    for (int j = 0; j < 4; j++)
                        if (gc + j < N) pv[j] = B[(long)(kn + krow) * N + gc + j];
                }
                rb[i] = v;
            }
        }

        // ---- 4 k8-steps ----
#pragma unroll
        for (int ks = 0; ks < 4; ks++) {
            int kb = ks * 8;
            int kA0 = kb + qc;
            int kA1 = kb + qc + 4;
            int sw0 = ((kA0 >> 2) & 7) << 3;
            int sw1 = ((kA1 >> 2) & 7) << 3;

            uint32_t a[2][4];
#pragma unroll
            for (int i = 0; i < 2; i++) {
                int mb = wm + i * 16;
                a[i][0] = __float_as_uint(As[kA0 * ASTRIDE + ((mb + qr)     ^ sw0)]);
                a[i][1] = __float_as_uint(As[kA0 * ASTRIDE + ((mb + qr + 8) ^ sw0)]);
                a[i][2] = __float_as_uint(As[kA1 * ASTRIDE + ((mb + qr)     ^ sw1)]);
                a[i][3] = __float_as_uint(As[kA1 * ASTRIDE + ((mb + qr + 8) ^ sw1)]);
            }
            uint32_t b[NJ][2];
#pragma unroll
            for (int j = 0; j < NJ; j++) {
                int nb = wn + j * 8;
                b[j][0] = __float_as_uint(Bs[(kb + qc)     * BSTR + nb + qr]);
                b[j][1] = __float_as_uint(Bs[(kb + qc + 4) * BSTR + nb + qr]);
            }
#pragma unroll
            for (int i = 0; i < 2; i++)
#pragma unroll
                for (int j = 0; j < NJ; j++)
                    mma_tf32(acc[i][j], a[i], b[j]);
        }
        __syncthreads();
    }

    // ---- epilogue ----
#pragma unroll
    for (int i = 0; i < 2; i++) {
        int r0 = bm + wm + i * 16 + qr;
        int r1 = r0 + 8;
#pragma unroll
        for (int j = 0; j < NJ; j++) {
            int c0 = bn + wn + j * 8 + qc * 2;
            float v0 = acc[i][j][0], v1 = acc[i][j][1];
            float v2 = acc[i][j][2], v3 = acc[i][j][3];
            if (EPI == 1) {
                float bb0 = (c0 < N) ? bias[c0] : 0.f;
                float bb1 = (c0 + 1 < N) ? bias[c0 + 1] : 0.f;
                v0 = rnd_tf32(fmaxf(v0 + bb0, 0.f));
                v1 = rnd_tf32(fmaxf(v1 + bb1, 0.f));
                v2 = rnd_tf32(fmaxf(v2 + bb0, 0.f));
                v3 = rnd_tf32(fmaxf(v3 + bb1, 0.f));
            }
            if (EPI == 2) {
                // fp16 store; N is even and c0 even -> pairs fully in/out
                __half* C16 = reinterpret_cast<__half*>(C);
                if (c0 + 1 < N) {
                    if (r0 < M)
                        *reinterpret_cast<__half2*>(C16 + (long)r0 * N + c0) =
                            __floats2half2_rn(v0, v1);
                    if (r1 < M)
                        *reinterpret_cast<__half2*>(C16 + (long)r1 * N + c0) =
                            __floats2half2_rn(v2, v3);
                }
            } else {
                if (r0 < M) {
                    if (c0     < N) C[(long)r0 * N + c0]     = v0;
                    if (c0 + 1 < N) C[(long)r0 * N + c0 + 1] = v1;
                }
                if (r1 < M) {
                    if (c0     < N) C[(long)r1 * N + c0]     = v2;
                    if (c0 + 1 < N) C[(long)r1 * N + c0 + 1] = v3;
                }
            }
        }
    }
}

// =========================================================
// weight prep (tf32 round) + degree zeroing, merged
// =========================================================
__global__ void prep_kernel(const float* __restrict__ W1,
                            const float* __restrict__ W2,
                            const float* __restrict__ W3)
{
    int i = blockIdx.x * blockDim.x + threadIdx.x;
    if (i < IN_CH * HID)  g_w1[i] = rnd_tf32(W1[i]);
    if (i < HID * HID)    g_w2[i] = rnd_tf32(W2[i]);
    if (i < HID * OUT_CH) g_w3[i] = rnd_tf32(W3[i]);
    if (i < N_NODES)      g_deg[i] = 0;
}

// convert x (fp32) -> fp16 into g_h16a
__global__ void xcvt_kernel(const float* __restrict__ x)
{
    int i = blockIdx.x * blockDim.x + threadIdx.x;
    if (i < N_NODES * IN_CH / 2) {
        float2 f = reinterpret_cast<const float2*>(x)[i];
        reinterpret_cast<__half2*>(g_h16a)[i] = __floats2half2_rn(f.x, f.y);
    }
}

// =========================================================
// CSR build: hist -> block scan -> finalize(+top scan) -> fill
// =========================================================
__global__ void hist_kernel(const int* __restrict__ dst)
{
    int e = blockIdx.x * blockDim.x + threadIdx.x;
    if (e < N_EDGES) atomicAdd(&g_deg[dst[e]], 1);
}

__global__ __launch_bounds__(256) void scan_block_kernel()
{
    __shared__ int s[256];
    int t = threadIdx.x;
    int i = blockIdx.x * 256 + t;
    int v = (i < N_NODES) ? g_deg[i] : 0;
    s[t] = v;
    __syncthreads();
#pragma unroll
    for (int o = 1; o < 256; o <<= 1) {
        int add = (t >= o) ? s[t - o] : 0;
        __syncthreads();
        s[t] += add;
        __syncthreads();
    }
    if (i < N_NODES) g_off[i] = s[t] - v;
    if (t == 255) g_bsum[blockIdx.x] = s[255];
}

__global__ __launch_bounds__(256) void scan_finalize_kernel()
{
    __shared__ int s[256];
    int t = threadIdx.x;
    int v = (t < NSB) ? g_bsum[t] : 0;
    s[t] = v;
    __syncthreads();
#pragma unroll
    for (int o = 1; o < 256; o <<= 1) {
        int add = (t >= o) ? s[t - o] : 0;
        __syncthreads();
        s[t] += add;
        __syncthreads();
    }
    int boff = s[blockIdx.x] - g_bsum[blockIdx.x];
    int i = blockIdx.x * 256 + t;
    if (i < N_NODES) {
        int o = g_off[i] + boff;
        g_off[i] = o;
        g_pos[i] = o;
    }
    if (i == 0) g_off[N_NODES] = N_EDGES;
}

__global__ void fill_kernel(const int* __restrict__ src,
                            const int* __restrict__ dst,
                            const float* __restrict__ ew)
{
    int e = blockIdx.x * blockDim.x + threadIdx.x;
    if (e >= N_EDGES) return;
    int p = atomicAdd(&g_pos[dst[e]], 1);
    g_csr[p] = make_int2(src[e], __float_as_int(ew[e]));
}

// =========================================================
// fp16 CSR gathers (fp32 accumulate)
// =========================================================

// 128-ch fp16 gather: one warp per node, lane holds 4 channels (uint2).
// out: rnd_tf32(acc) fp32
__global__ __launch_bounds__(256) void gather128h_kernel(float* __restrict__ agg)
{
    int n = (int)(((long)blockIdx.x * blockDim.x + threadIdx.x) >> 5);
    int lane = threadIdx.x & 31;
    if (n >= N_NODES) return;

    const uint2* hp = reinterpret_cast<const uint2*>(g_h16a);  // 32 uint2 per row
    int e   = g_off[n];
    int end = g_off[n + 1];

    float4 acc = make_float4(0.f, 0.f, 0.f, 0.f);
    for (; e + 1 < end; e += 2) {
        int2 t0 = g_csr[e];
        int2 t1 = g_csr[e + 1];
        float w0 = __int_as_float(t0.y);
        float w1 = __int_as_float(t1.y);
        uint2 v0 = hp[(long)t0.x * 32 + lane];
        uint2 v1 = hp[(long)t1.x * 32 + lane];
        float2 a0 = __half22float2(*reinterpret_cast<__half2*>(&v0.x));
        float2 a1 = __half22float2(*reinterpret_cast<__half2*>(&v0.y));
        float2 b0 = __half22float2(*reinterpret_cast<__half2*>(&v1.x));
        float2 b1 = __half22float2(*reinterpret_cast<__half2*>(&v1.y));
        acc.x += w0 * a0.x + w1 * b0.x;
        acc.y += w0 * a0.y + w1 * b0.y;
        acc.z += w0 * a1.x + w1 * b1.x;
        acc.w += w0 * a1.y + w1 * b1.y;
    }
    if (e < end) {
        int2 t0 = g_csr[e];
        float w0 = __int_as_float(t0.y);
        uint2 v0 = hp[(long)t0.x * 32 + lane];
        float2 a0 = __half22float2(*reinterpret_cast<__half2*>(&v0.x));
        float2 a1 = __half22float2(*reinterpret_cast<__half2*>(&v0.y));
        acc.x += w0 * a0.x;
        acc.y += w0 * a0.y;
        acc.z += w0 * a1.x;
        acc.w += w0 * a1.y;
    }

    acc.x = rnd_tf32(acc.x);
    acc.y = rnd_tf32(acc.y);
    acc.z = rnd_tf32(acc.z);
    acc.w = rnd_tf32(acc.w);
    reinterpret_cast<float4*>(agg)[(long)n * 32 + lane] = acc;
}

// 256-ch fp16 gather: one warp per node, lane holds 8 channels (uint4).
// out: rnd_tf32(relu(acc + bias)) fp32
__global__ __launch_bounds__(256) void gather256h_kernel(
    const float* __restrict__ bias, float* __restrict__ agg)
{
    int n = (int)(((long)blockIdx.x * blockDim.x + threadIdx.x) >> 5);
    int lane = threadIdx.x & 31;
    if (n >= N_NODES) return;
    int c8 = lane * 8;

    const uint4* hp = reinterpret_cast<const uint4*>(g_h16a);  // 32 uint4 per row
    int e   = g_off[n];
    int end = g_off[n + 1];

    float acc[8];
#pragma unroll
    for (int t = 0; t < 8; t++) acc[t] = 0.f;

    for (; e < end; e++) {
        int2 t0 = g_csr[e];
        float w0 = __int_as_float(t0.y);
        uint4 v = hp[(long)t0.x * 32 + lane];
        float2 f0 = __half22float2(*reinterpret_cast<__half2*>(&v.x));
        float2 f1 = __half22float2(*reinterpret_cast<__half2*>(&v.y));
        float2 f2 = __half22float2(*reinterpret_cast<__half2*>(&v.z));
        float2 f3 = __half22float2(*reinterpret_cast<__half2*>(&v.w));
        acc[0] += w0 * f0.x; acc[1] += w0 * f0.y;
        acc[2] += w0 * f1.x; acc[3] += w0 * f1.y;
        acc[4] += w0 * f2.x; acc[5] += w0 * f2.y;
        acc[6] += w0 * f3.x; acc[7] += w0 * f3.y;
    }

    float4 bb0 = *reinterpret_cast<const float4*>(bias + c8);
    float4 bb1 = *reinterpret_cast<const float4*>(bias + c8 + 4);
    float4 o0, o1;
    o0.x = rnd_tf32(fmaxf(acc[0] + bb0.x, 0.f));
    o0.y = rnd_tf32(fmaxf(acc[1] + bb0.y, 0.f));
    o0.z = rnd_tf32(fmaxf(acc[2] + bb0.z, 0.f));
    o0.w = rnd_tf32(fmaxf(acc[3] + bb0.w, 0.f));
    o1.x = rnd_tf32(fmaxf(acc[4] + bb1.x, 0.f));
    o1.y = rnd_tf32(fmaxf(acc[5] + bb1.y, 0.f));
    o1.z = rnd_tf32(fmaxf(acc[6] + bb1.z, 0.f));
    o1.w = rnd_tf32(fmaxf(acc[7] + bb1.w, 0.f));

    float4* op = reinterpret_cast<float4*>(agg + (long)n * 256 + c8);
    op[0] = o0;
    op[1] = o1;
}

// =========================================================
// Fused layer-3 aggregation + bias + log_softmax (fp16 input).
// One warp per node: lane < 20 holds channels (2*lane, 2*lane+1).
// =========================================================
__global__ __launch_bounds__(256) void gather40h_lsm_kernel(
    const float* __restrict__ b, float* __restrict__ out)
{
    int n = (int)(((long)blockIdx.x * blockDim.x + threadIdx.x) >> 5);
    int lane = threadIdx.x & 31;
    if (n >= N_NODES) return;

    const __half2* hp = reinterpret_cast<const __half2*>(g_h16b);  // 20 half2 per row
    int e   = g_off[n];
    int end = g_off[n + 1];
    float acc0 = 0.f, acc1 = 0.f;

    if (lane < 20) {
        for (; e + 1 < end; e += 2) {
            int2 t0 = g_csr[e];
            int2 t1 = g_csr[e + 1];
            float w0 = __int_as_float(t0.y);
            float w1 = __int_as_float(t1.y);
            float2 f0 = __half22float2(hp[(long)t0.x * 20 + lane]);
            float2 f1 = __half22float2(hp[(long)t1.x * 20 + lane]);
            acc0 += w0 * f0.x + w1 * f1.x;
            acc1 += w0 * f0.y + w1 * f1.y;
        }
        if (e < end) {
            int2 t0 = g_csr[e];
            float w0 = __int_as_float(t0.y);
            float2 f0 = __half22float2(hp[(long)t0.x * 20 + lane]);
            acc0 += w0 * f0.x;
            acc1 += w0 * f0.y;
        }
    }

    float v0 = (lane < 20) ? (acc0 + b[2 * lane])     : -INFINITY;
    float v1 = (lane < 20) ? (acc1 + b[2 * lane + 1]) : -INFINITY;

    float m = fmaxf(v0, v1);
#pragma unroll
    for (int o = 16; o > 0; o >>= 1)
        m = fmaxf(m, __shfl_xor_sync(0xFFFFFFFFu, m, o));

    float s = (lane < 20) ? (__expf(v0 - m) + __expf(v1 - m)) : 0.f;
#pragma unroll
    for (int o = 16; o > 0; o >>= 1)
        s += __shfl_xor_sync(0xFFFFFFFFu, s, o);

    float lse = m + logf(s);
    if (lane < 20) {
        float2 r = make_float2(v0 - lse, v1 - lse);
        *reinterpret_cast<float2*>(out + (long)n * OUT_CH + 2 * lane) = r;
    }
}

// ---------------------------------------------------------
// launch
// ---------------------------------------------------------
extern "C" void kernel_launch(void* const* d_in, const int* in_sizes, int n_in,
                              void* d_out, int out_size)
{
    const float* x  = (const float*)d_in[0];
    const int*   ei = (const int*)d_in[1];
    const float* ew = (const float*)d_in[2];
    const float* W1 = (const float*)d_in[3];
    const float* b1 = (const float*)d_in[4];
    const float* W2 = (const float*)d_in[5];
    const float* b2 = (const float*)d_in[6];
    const float* W3 = (const float*)d_in[7];
    const float* b3 = (const float*)d_in[8];
    float* out = (float*)d_out;

    const int* src = ei;
    const int* dst = ei + N_EDGES;

    float *buf0, *buf1, *w1p, *w2p, *w3p;
    __half *h16a, *h16b;
    cudaGetSymbolAddress((void**)&buf0, g_buf0);
    cudaGetSymbolAddress((void**)&buf1, g_buf1);
    cudaGetSymbolAddress((void**)&w1p, g_w1);
    cudaGetSymbolAddress((void**)&w2p, g_w2);
    cudaGetSymbolAddress((void**)&w3p, g_w3);
    cudaGetSymbolAddress((void**)&h16a, g_h16a);
    cudaGetSymbolAddress((void**)&h16b, g_h16b);

    const int mtiles = (N_NODES + GBM - 1) / GBM;   // 391
    dim3 grid_wide(HID / 128, mtiles);              // 2 x 391 (BN=128)
    dim3 grid_narrow(1, mtiles);                    // 1 x 391 (BN=64, N=40)
    const int nwarp_blocks = (N_NODES * 32 + 255) / 256;

    // weight prep (+deg zero), x->fp16, CSR build
    prep_kernel<<<(HID * HID + 255) / 256, 256>>>(W1, W2, W3);
    xcvt_kernel<<<(N_NODES * IN_CH / 2 + 255) / 256, 256>>>(x);
    hist_kernel<<<(N_EDGES + 255) / 256, 256>>>(dst);
    scan_block_kernel<<<NSB, 256>>>();
    scan_finalize_kernel<<<NSB, 256>>>();
    fill_kernel<<<(N_EDGES + 255) / 256, 256>>>(src, dst, ew);

    // ---- layer 1 (reordered): agg_x = A_hat @ x16 ; h1 = relu(agg_x @ W1 + b1) ----
    gather128h_kernel<<<nwarp_blocks, 256>>>(buf1);
    gemm_tf32<1, 128><<<grid_wide, 512>>>(buf1, w1p, b1, buf0, N_NODES, HID, IN_CH);

    // ---- layer 2: h2 = h1r @ W2 (fp16 out) ; agg2 = relu(A_hat @ h2 + b2) ----
    gemm_tf32<2, 128><<<grid_wide, 512>>>(buf0, w2p, nullptr, (float*)h16a, N_NODES, HID, HID);
    gather256h_kernel<<<nwarp_blocks, 256>>>(b2, buf1);

    // ---- layer 3: h3 = agg2r @ W3 (fp16 out) ; out = log_softmax(A_hat @ h3 + b3) ----
    gemm_tf32<2, 64><<<grid_narrow, 512>>>(buf1, w3p, nullptr, (float*)h16b, N_NODES, OUT_CH, HID);
    gather40h_lsm_kernel<<<nwarp_blocks, 256>>>(b3, out);
}

// round 17
// speedup vs baseline: 1.5267x; 1.3468x over previous
#include <cuda_runtime.h>
#include <cuda_bf16.h>
#include <cuda_fp16.h>
#include <math.h>
#include <stdint.h>

// Problem constants
#define N_NODES 50000
#define N_EDGES 800000
#define IN_CH   128
#define HID     256
#define OUT_CH  40

// -------- static device scratch (allocation-free) --------
// fp16 feature ping-pong buffers (N x 256 halves each)
__device__ __half g_ha[(size_t)N_NODES * HID];
__device__ __half g_hb[(size_t)N_NODES * HID];

// fp16 transposed weights: Wt[n][k]
__device__ __half g_w1t[HID * IN_CH];
__device__ __half g_w2t[HID * HID];
__device__ __half g_w3t[OUT_CH * HID];

// CSR-by-dst scratch (packed: .x = src, .y = float-bits of weight)
#define NSB ((N_NODES + 255) / 256)   // 196 scan blocks
__device__ int   g_deg[N_NODES];
__device__ int   g_off[N_NODES + 1];
__device__ int   g_pos[N_NODES];
__device__ int   g_bsum[NSB];
__device__ int2  g_csr[N_EDGES];

// =========================================================
// fp16 tensor-core GEMM: C[M,N] = A[M,K] @ W[K,N]
// A fp16 row-major [M][K]; Bt = W^T fp16 row-major [N][K].
// C fp16 [M][N].
// EPI: 1 = relu(acc + bias[n]) ; 2 = plain
// 512 threads = 16 warps (4M x 4N), block tile 128 x BN x 32,
// warp tile 32 x BN/4, mma.sync m16n8k16 f32 accum.
// Smem rows padded to 40 halves: fragment words hit banks
// (r*20+qc) mod 32 -> all 32 distinct, conflict-free.
// =========================================================
#define GBM 128
#define GBK 32
#define PSTR 40   // halves per smem row (32 + 8 pad)

__device__ __forceinline__ void mma_f16(float* d, const uint32_t* a, const uint32_t* b) {
    asm volatile(
        "mma.sync.aligned.m16n8k16.row.col.f32.f16.f16.f32 "
        "{%0,%1,%2,%3}, {%4,%5,%6,%7}, {%8,%9}, {%0,%1,%2,%3};\n"
        : "+f"(d[0]), "+f"(d[1]), "+f"(d[2]), "+f"(d[3])
        : "r"(a[0]), "r"(a[1]), "r"(a[2]), "r"(a[3]),
          "r"(b[0]), "r"(b[1]));
}

template <int EPI, int BN>
__global__ __launch_bounds__(512) void gemm_f16(
    const __half* __restrict__ A, const __half* __restrict__ Bt,
    const float* __restrict__ bias, __half* __restrict__ C,
    int M, int N, int K)
{
    constexpr int WN  = BN / 4;        // warp N-tile
    constexpr int NJ  = BN / 32;       // 8-col groups per warp
    constexpr int BT4 = BN * 4;        // uint4 loads for B tile (BN rows * 4/row)

    __shared__ __align__(16) __half Ah[GBM * PSTR];
    __shared__ __align__(16) __half Bh[BN * PSTR];

    const int tid  = threadIdx.x;
    const int warp = tid >> 5;
    const int lane = tid & 31;
    const int bm = blockIdx.y * GBM;
    const int bn = blockIdx.x * BN;

    const int wm = (warp >> 2) * 32;
    const int wn = (warp & 3) * WN;
    const int qr = lane >> 2;
    const int qc = lane & 3;

    // A tile: 128 rows x 32 halves = 512 uint4; 1 per thread
    const int arow = tid >> 2;
    const int aks  = (tid & 3) * 8;

    float acc[2][NJ][4];
#pragma unroll
    for (int i = 0; i < 2; i++)
#pragma unroll
        for (int j = 0; j < NJ; j++)
#pragma unroll
            for (int t = 0; t < 4; t++) acc[i][j][t] = 0.f;

    uint4 ra, rb;
    const uint4 Z = make_uint4(0u, 0u, 0u, 0u);

    // ---- preload tile k0 = 0 ----
    {
        int gr = bm + arow;
        ra = (gr < M) ? *reinterpret_cast<const uint4*>(A + (long)gr * K + aks) : Z;
        rb = Z;
        if (tid < BT4) {
            int brow = tid >> 2;
            int bks  = (tid & 3) * 8;
            int gn = bn + brow;
            if (gn < N) rb = *reinterpret_cast<const uint4*>(Bt + (long)gn * K + bks);
        }
    }

    for (int k0 = 0; k0 < K; k0 += GBK) {
        // ---- store regs -> smem ----
        *reinterpret_cast<uint4*>(Ah + arow * PSTR + aks) = ra;
        if (tid < BT4) {
            int brow = tid >> 2;
            int bks  = (tid & 3) * 8;
            *reinterpret_cast<uint4*>(Bh + brow * PSTR + bks) = rb;
        }
        __syncthreads();

        // ---- prefetch next tile while mma runs ----
        if (k0 + GBK < K) {
            int kn = k0 + GBK;
            int gr = bm + arow;
            ra = (gr < M) ? *reinterpret_cast<const uint4*>(A + (long)gr * K + kn + aks) : Z;
            if (tid < BT4) {
                int brow = tid >> 2;
                int bks  = (tid & 3) * 8;
                int gn = bn + brow;
                rb = (gn < N) ? *reinterpret_cast<const uint4*>(Bt + (long)gn * K + kn + bks) : Z;
            }
        }

        // ---- 2 k16-steps ----
#pragma unroll
        for (int ks = 0; ks < 2; ks++) {
            int kb = ks * 16 + qc * 2;

            uint32_t a[2][4];
#pragma unroll
            for (int i = 0; i < 2; i++) {
                const __half* ap = Ah + (wm + i * 16 + qr) * PSTR + kb;
                a[i][0] = *reinterpret_cast<const uint32_t*>(ap);
                a[i][1] = *reinterpret_cast<const uint32_t*>(ap + 8 * PSTR);
                a[i][2] = *reinterpret_cast<const uint32_t*>(ap + 8);
                a[i][3] = *reinterpret_cast<const uint32_t*>(ap + 8 * PSTR + 8);
            }
            uint32_t b[NJ][2];
#pragma unroll
            for (int j = 0; j < NJ; j++) {
                const __half* bp = Bh + (wn + j * 8 + qr) * PSTR + kb;
                b[j][0] = *reinterpret_cast<const uint32_t*>(bp);
                b[j][1] = *reinterpret_cast<const uint32_t*>(bp + 8);
            }
#pragma unroll
            for (int i = 0; i < 2; i++)
#pragma unroll
                for (int j = 0; j < NJ; j++)
                    mma_f16(acc[i][j], a[i], b[j]);
        }
        __syncthreads();
    }

    // ---- epilogue: fp16 store (pairs are adjacent cols) ----
#pragma unroll
    for (int i = 0; i < 2; i++) {
        int r0 = bm + wm + i * 16 + qr;
        int r1 = r0 + 8;
#pragma unroll
        for (int j = 0; j < NJ; j++) {
            int c0 = bn + wn + j * 8 + qc * 2;
            if (c0 + 1 >= N) continue;
            float v0 = acc[i][j][0], v1 = acc[i][j][1];
            float v2 = acc[i][j][2], v3 = acc[i][j][3];
            if (EPI == 1) {
                float bb0 = bias[c0];
                float bb1 = bias[c0 + 1];
                v0 = fmaxf(v0 + bb0, 0.f);
                v1 = fmaxf(v1 + bb1, 0.f);
                v2 = fmaxf(v2 + bb0, 0.f);
                v3 = fmaxf(v3 + bb1, 0.f);
            }
            if (r0 < M)
                *reinterpret_cast<__half2*>(C + (long)r0 * N + c0) = __floats2half2_rn(v0, v1);
            if (r1 < M)
                *reinterpret_cast<__half2*>(C + (long)r1 * N + c0) = __floats2half2_rn(v2, v3);
        }
    }
}

// =========================================================
// weight prep: fp16 transpose; + degree zeroing
// =========================================================
__global__ void prep_kernel(const float* __restrict__ W1,
                            const float* __restrict__ W2,
                            const float* __restrict__ W3)
{
    int i = blockIdx.x * blockDim.x + threadIdx.x;
    if (i < IN_CH * HID) {          // w1t[n][k], n<HID, k<IN_CH
        int n = i / IN_CH, k = i % IN_CH;
        g_w1t[i] = __float2half_rn(W1[k * HID + n]);
    }
    if (i < HID * HID) {            // w2t[n][k]
        int n = i / HID, k = i % HID;
        g_w2t[i] = __float2half_rn(W2[k * HID + n]);
    }
    if (i < OUT_CH * HID) {         // w3t[n][k], n<OUT_CH, k<HID
        int n = i / HID, k = i % HID;
        g_w3t[i] = __float2half_rn(W3[k * OUT_CH + n]);
    }
    if (i < N_NODES) g_deg[i] = 0;
}

// convert x (fp32) -> fp16 into g_ha
__global__ void xcvt_kernel(const float* __restrict__ x)
{
    int i = blockIdx.x * blockDim.x + threadIdx.x;
    if (i < N_NODES * IN_CH / 2) {
        float2 f = reinterpret_cast<const float2*>(x)[i];
        reinterpret_cast<__half2*>(g_ha)[i] = __floats2half2_rn(f.x, f.y);
    }
}

// =========================================================
// CSR build: hist -> block scan -> finalize(+top scan) -> fill
// =========================================================
__global__ void hist_kernel(const int* __restrict__ dst)
{
    int e = blockIdx.x * blockDim.x + threadIdx.x;
    if (e < N_EDGES) atomicAdd(&g_deg[dst[e]], 1);
}

__global__ __launch_bounds__(256) void scan_block_kernel()
{
    __shared__ int s[256];
    int t = threadIdx.x;
    int i = blockIdx.x * 256 + t;
    int v = (i < N_NODES) ? g_deg[i] : 0;
    s[t] = v;
    __syncthreads();
#pragma unroll
    for (int o = 1; o < 256; o <<= 1) {
        int add = (t >= o) ? s[t - o] : 0;
        __syncthreads();
        s[t] += add;
        __syncthreads();
    }
    if (i < N_NODES) g_off[i] = s[t] - v;
    if (t == 255) g_bsum[blockIdx.x] = s[255];
}

__global__ __launch_bounds__(256) void scan_finalize_kernel()
{
    __shared__ int s[256];
    int t = threadIdx.x;
    int v = (t < NSB) ? g_bsum[t] : 0;
    s[t] = v;
    __syncthreads();
#pragma unroll
    for (int o = 1; o < 256; o <<= 1) {
        int add = (t >= o) ? s[t - o] : 0;
        __syncthreads();
        s[t] += add;
        __syncthreads();
    }
    int boff = s[blockIdx.x] - g_bsum[blockIdx.x];
    int i = blockIdx.x * 256 + t;
    if (i < N_NODES) {
        int o = g_off[i] + boff;
        g_off[i] = o;
        g_pos[i] = o;
    }
    if (i == 0) g_off[N_NODES] = N_EDGES;
}

__global__ void fill_kernel(const int* __restrict__ src,
                            const int* __restrict__ dst,
                            const float* __restrict__ ew)
{
    int e = blockIdx.x * blockDim.x + threadIdx.x;
    if (e >= N_EDGES) return;
    int p = atomicAdd(&g_pos[dst[e]], 1);
    g_csr[p] = make_int2(src[e], __float_as_int(ew[e]));
}

// =========================================================
// fp16 CSR gathers (fp32 accumulate, fp16 output)
// =========================================================

// 128-ch: one warp per node, lane holds 4 channels. g_ha -> g_hb.
__global__ __launch_bounds__(256) void gather128h_kernel()
{
    int n = (int)(((long)blockIdx.x * blockDim.x + threadIdx.x) >> 5);
    int lane = threadIdx.x & 31;
    if (n >= N_NODES) return;

    const uint2* hp = reinterpret_cast<const uint2*>(g_ha);  // 32 uint2 per row
    int e   = g_off[n];
    int end = g_off[n + 1];

    float4 acc = make_float4(0.f, 0.f, 0.f, 0.f);
    for (; e + 1 < end; e += 2) {
        int2 t0 = g_csr[e];
        int2 t1 = g_csr[e + 1];
        float w0 = __int_as_float(t0.y);
        float w1 = __int_as_float(t1.y);
        uint2 v0 = hp[(long)t0.x * 32 + lane];
        uint2 v1 = hp[(long)t1.x * 32 + lane];
        float2 a0 = __half22float2(*reinterpret_cast<__half2*>(&v0.x));
        float2 a1 = __half22float2(*reinterpret_cast<__half2*>(&v0.y));
        float2 b0 = __half22float2(*reinterpret_cast<__half2*>(&v1.x));
        float2 b1 = __half22float2(*reinterpret_cast<__half2*>(&v1.y));
        acc.x += w0 * a0.x + w1 * b0.x;
        acc.y += w0 * a0.y + w1 * b0.y;
        acc.z += w0 * a1.x + w1 * b1.x;
        acc.w += w0 * a1.y + w1 * b1.y;
    }
    if (e < end) {
        int2 t0 = g_csr[e];
        float w0 = __int_as_float(t0.y);
        uint2 v0 = hp[(long)t0.x * 32 + lane];
        float2 a0 = __half22float2(*reinterpret_cast<__half2*>(&v0.x));
        float2 a1 = __half22float2(*reinterpret_cast<__half2*>(&v0.y));
        acc.x += w0 * a0.x;
        acc.y += w0 * a0.y;
        acc.z += w0 * a1.x;
        acc.w += w0 * a1.y;
    }

    uint2 o;
    *reinterpret_cast<__half2*>(&o.x) = __floats2half2_rn(acc.x, acc.y);
    *reinterpret_cast<__half2*>(&o.y) = __floats2half2_rn(acc.z, acc.w);
    reinterpret_cast<uint2*>(g_hb)[(long)n * 32 + lane] = o;
}

// 256-ch: one warp per node, lane holds 8 channels. g_hb -> g_ha,
// epi relu(acc + bias).
__global__ __launch_bounds__(256) void gather256h_kernel(const float* __restrict__ bias)
{
    int n = (int)(((long)blockIdx.x * blockDim.x + threadIdx.x) >> 5);
    int lane = threadIdx.x & 31;
    if (n >= N_NODES) return;
    int c8 = lane * 8;

    const uint4* hp = reinterpret_cast<const uint4*>(g_hb);  // 32 uint4 per row
    int e   = g_off[n];
    int end = g_off[n + 1];

    float acc[8];
#pragma unroll
    for (int t = 0; t < 8; t++) acc[t] = 0.f;

    for (; e < end; e++) {
        int2 t0 = g_csr[e];
        float w0 = __int_as_float(t0.y);
        uint4 v = hp[(long)t0.x * 32 + lane];
        float2 f0 = __half22float2(*reinterpret_cast<__half2*>(&v.x));
        float2 f1 = __half22float2(*reinterpret_cast<__half2*>(&v.y));
        float2 f2 = __half22float2(*reinterpret_cast<__half2*>(&v.z));
        float2 f3 = __half22float2(*reinterpret_cast<__half2*>(&v.w));
        acc[0] += w0 * f0.x; acc[1] += w0 * f0.y;
        acc[2] += w0 * f1.x; acc[3] += w0 * f1.y;
        acc[4] += w0 * f2.x; acc[5] += w0 * f2.y;
        acc[6] += w0 * f3.x; acc[7] += w0 * f3.y;
    }

    float4 bb0 = *reinterpret_cast<const float4*>(bias + c8);
    float4 bb1 = *reinterpret_cast<const float4*>(bias + c8 + 4);
    uint4 o;
    *reinterpret_cast<__half2*>(&o.x) =
        __floats2half2_rn(fmaxf(acc[0] + bb0.x, 0.f), fmaxf(acc[1] + bb0.y, 0.f));
    *reinterpret_cast<__half2*>(&o.y) =
        __floats2half2_rn(fmaxf(acc[2] + bb0.z, 0.f), fmaxf(acc[3] + bb0.w, 0.f));
    *reinterpret_cast<__half2*>(&o.z) =
        __floats2half2_rn(fmaxf(acc[4] + bb1.x, 0.f), fmaxf(acc[5] + bb1.y, 0.f));
    *reinterpret_cast<__half2*>(&o.w) =
        __floats2half2_rn(fmaxf(acc[6] + bb1.z, 0.f), fmaxf(acc[7] + bb1.w, 0.f));
    reinterpret_cast<uint4*>(g_ha)[(long)n * 32 + lane] = o;
}

// =========================================================
// Fused layer-3 aggregation + bias + log_softmax (fp16 h3 in g_hb).
// One warp per node: lane < 20 holds channels (2*lane, 2*lane+1).
// =========================================================
__global__ __launch_bounds__(256) void gather40h_lsm_kernel(
    const float* __restrict__ b, float* __restrict__ out)
{
    int n = (int)(((long)blockIdx.x * blockDim.x + threadIdx.x) >> 5);
    int lane = threadIdx.x & 31;
    if (n >= N_NODES) return;

    const __half2* hp = reinterpret_cast<const __half2*>(g_hb);  // 20 half2 per row
    int e   = g_off[n];
    int end = g_off[n + 1];
    float acc0 = 0.f, acc1 = 0.f;

    if (lane < 20) {
        for (; e + 1 < end; e += 2) {
            int2 t0 = g_csr[e];
            int2 t1 = g_csr[e + 1];
            float w0 = __int_as_float(t0.y);
            float w1 = __int_as_float(t1.y);
            float2 f0 = __half22float2(hp[(long)t0.x * 20 + lane]);
            float2 f1 = __half22float2(hp[(long)t1.x * 20 + lane]);
            acc0 += w0 * f0.x + w1 * f1.x;
            acc1 += w0 * f0.y + w1 * f1.y;
        }
        if (e < end) {
            int2 t0 = g_csr[e];
            float w0 = __int_as_float(t0.y);
            float2 f0 = __half22float2(hp[(long)t0.x * 20 + lane]);
            acc0 += w0 * f0.x;
            acc1 += w0 * f0.y;
        }
    }

    float v0 = (lane < 20) ? (acc0 + b[2 * lane])     : -INFINITY;
    float v1 = (lane < 20) ? (acc1 + b[2 * lane + 1]) : -INFINITY;

    float m = fmaxf(v0, v1);
#pragma unroll
    for (int o = 16; o > 0; o >>= 1)
        m = fmaxf(m, __shfl_xor_sync(0xFFFFFFFFu, m, o));

    float s = (lane < 20) ? (__expf(v0 - m) + __expf(v1 - m)) : 0.f;
#pragma unroll
    for (int o = 16; o > 0; o >>= 1)
        s += __shfl_xor_sync(0xFFFFFFFFu, s, o);

    float lse = m + logf(s);
    if (lane < 20) {
        float2 r = make_float2(v0 - lse, v1 - lse);
        *reinterpret_cast<float2*>(out + (long)n * OUT_CH + 2 * lane) = r;
    }
}

// ---------------------------------------------------------
// launch
// ---------------------------------------------------------
extern "C" void kernel_launch(void* const* d_in, const int* in_sizes, int n_in,
                              void* d_out, int out_size)
{
    const float* x  = (const float*)d_in[0];
    const int*   ei = (const int*)d_in[1];
    const float* ew = (const float*)d_in[2];
    const float* W1 = (const float*)d_in[3];
    const float* b1 = (const float*)d_in[4];
    const float* W2 = (const float*)d_in[5];
    const float* b2 = (const float*)d_in[6];
    const float* W3 = (const float*)d_in[7];
    const float* b3 = (const float*)d_in[8];
    float* out = (float*)d_out;

    const int* src = ei;
    const int* dst = ei + N_EDGES;

    __half *ha, *hb, *w1t, *w2t, *w3t;
    cudaGetSymbolAddress((void**)&ha, g_ha);
    cudaGetSymbolAddress((void**)&hb, g_hb);
    cudaGetSymbolAddress((void**)&w1t, g_w1t);
    cudaGetSymbolAddress((void**)&w2t, g_w2t);
    cudaGetSymbolAddress((void**)&w3t, g_w3t);

    const int mtiles = (N_NODES + GBM - 1) / GBM;   // 391
    dim3 grid_wide(HID / 128, mtiles);              // 2 x 391 (BN=128)
    dim3 grid_narrow(1, mtiles);                    // 1 x 391 (BN=64, N=40)
    const int nwarp_blocks = (N_NODES * 32 + 255) / 256;

    // weight prep (+deg zero), x->fp16, CSR build
    prep_kernel<<<(HID * HID + 255) / 256, 256>>>(W1, W2, W3);
    xcvt_kernel<<<(N_NODES * IN_CH / 2 + 255) / 256, 256>>>(x);
    hist_kernel<<<(N_EDGES + 255) / 256, 256>>>(dst);
    scan_block_kernel<<<NSB, 256>>>();
    scan_finalize_kernel<<<NSB, 256>>>();
    fill_kernel<<<(N_EDGES + 255) / 256, 256>>>(src, dst, ew);

    // ---- layer 1 (reordered): agg_x = A_hat @ x16 (ha->hb);
    //      h1 = relu(agg_x @ W1 + b1) fp16 (hb->ha) ----
    gather128h_kernel<<<nwarp_blocks, 256>>>();
    gemm_f16<1, 128><<<grid_wide, 512>>>(hb, w1t, b1, ha, N_NODES, HID, IN_CH);

    // ---- layer 2: h2 = h1r @ W2 (ha->hb) ; agg2 = relu(A_hat @ h2 + b2) (hb->ha) ----
    gemm_f16<2, 128><<<grid_wide, 512>>>(ha, w2t, nullptr, hb, N_NODES, HID, HID);
    gather256h_kernel<<<nwarp_blocks, 256>>>(b2);

    // ---- layer 3: h3 = agg2r @ W3 (ha->hb) ; out = log_softmax(A_hat @ h3 + b3) ----
    gemm_f16<2, 64><<<grid_narrow, 512>>>(ha, w3t, nullptr, hb, N_NODES, OUT_CH, HID);
    gather40h_lsm_kernel<<<nwarp_blocks, 256>>>(b3, out);
}